// round 10
// baseline (speedup 1.0000x reference)
#include <cuda_runtime.h>
#include <cuda_fp16.h>
#include <cstdint>

#define NN 100000
#define EE 1600000
#define D 64
#define MAXD 96
#define EPSF 1e-9f
#define IMAX 0x7fffffff

// ---- static device scratch (no allocation allowed) ----
// f32 arrays: epilogue own-row reads/writes. fp16 mirrors: gathered (row NN = zero sentinel).
__device__ float g_h[(NN + 1) * D];
__device__ float g_A1[(NN + 1) * D];
__device__ float g_A2[(NN + 1) * D];
__device__ float g_Suh[NN * D];
__device__ float g_SuA1[NN * D];
__device__ __half g_h16[(NN + 1) * D];
__device__ __half g_A116[(NN + 1) * D];
__device__ __half g_A216[(NN + 1) * D];
__device__ __half g_A316[(NN + 1) * D];
__device__ int   g_deg[NN];
__device__ int   g_cursor[NN];
__device__ float g_u[NN + 1];
__device__ float g_Su[NN];
__device__ float g_Su2[NN];
__device__ int   g_csr[(size_t)NN * MAXD];   // byte offsets (s * 128) after sortu
__device__ float g_uS[(size_t)NN * MAXD];    // u values aligned with sorted csr

__device__ __forceinline__ void store8h(__half* p, const float* v) {
    __half2 h0 = __floats2half2_rn(v[0], v[1]);
    __half2 h1 = __floats2half2_rn(v[2], v[3]);
    __half2 h2 = __floats2half2_rn(v[4], v[5]);
    __half2 h3 = __floats2half2_rn(v[6], v[7]);
    uint4 r;
    r.x = *(unsigned int*)&h0; r.y = *(unsigned int*)&h1;
    r.z = *(unsigned int*)&h2; r.w = *(unsigned int*)&h3;
    *(uint4*)p = r;
}

// ---------------- h = x @ W + b  (f32 + fp16; zero cursor + fp16 sentinels) ----------------
__global__ void k_gemm(const float* __restrict__ x, const float* __restrict__ W,
                       const float* __restrict__ b) {
    __shared__ float Ws[D * D];
    __shared__ float bs[D];
    for (int i = threadIdx.x; i < D * D; i += blockDim.x) Ws[i] = W[i];
    if (threadIdx.x < D) bs[threadIdx.x] = b[threadIdx.x];
    __syncthreads();
    int row = blockIdx.x * blockDim.x + threadIdx.x;
    if (blockIdx.x == 0 && threadIdx.x < D) {
        g_h[NN * D + threadIdx.x] = 0.f;
        g_h16[NN * D + threadIdx.x] = __float2half(0.f);
        g_A116[NN * D + threadIdx.x] = __float2half(0.f);
        g_A216[NN * D + threadIdx.x] = __float2half(0.f);
        g_A316[NN * D + threadIdx.x] = __float2half(0.f);
        if (threadIdx.x == 0) g_u[NN] = 0.f;
    }
    if (row >= NN) return;
    g_cursor[row] = 0;
    float acc[D];
#pragma unroll
    for (int j = 0; j < D; j++) acc[j] = bs[j];
    const float4* xr = (const float4*)(x + (size_t)row * D);
#pragma unroll 2
    for (int k4 = 0; k4 < 16; k4++) {
        float4 xv = xr[k4];
#pragma unroll
        for (int kk = 0; kk < 4; kk++) {
            float xk = (kk == 0) ? xv.x : (kk == 1) ? xv.y : (kk == 2) ? xv.z : xv.w;
            const float4* wr = (const float4*)&Ws[(k4 * 4 + kk) * D];
#pragma unroll
            for (int j4 = 0; j4 < 16; j4++) {
                float4 w = wr[j4];
                acc[j4 * 4 + 0] += xk * w.x;
                acc[j4 * 4 + 1] += xk * w.y;
                acc[j4 * 4 + 2] += xk * w.z;
                acc[j4 * 4 + 3] += xk * w.w;
            }
        }
    }
    float4* hr = (float4*)(g_h + (size_t)row * D);
#pragma unroll
    for (int j4 = 0; j4 < 16; j4++)
        hr[j4] = make_float4(acc[j4 * 4], acc[j4 * 4 + 1], acc[j4 * 4 + 2], acc[j4 * 4 + 3]);
#pragma unroll
    for (int j = 0; j < 8; j++)
        store8h(g_h16 + (size_t)row * D + j * 8, acc + j * 8);
}

// ---------------- CSR fill ----------------
__global__ void k_fill(const int* __restrict__ src, const int* __restrict__ dst) {
    int e = blockIdx.x * blockDim.x + threadIdx.x;
    if (e >= EE) return;
    int d = dst[e];
    int pos = atomicAdd(&g_cursor[d], 1);
    if (pos < MAXD) g_csr[(size_t)d * MAXD + pos] = src[e];
}

// ---------------- per-node u + deg ----------------
__global__ void k_u(const float* __restrict__ lm) {
    int i = blockIdx.x * blockDim.x + threadIdx.x;
    if (i >= NN) return;
    int dg = min(g_cursor[i], MAXD);
    g_deg[i] = dg;
    g_u[i] = (dg <= 1) ? 0.f : lm[0] / ((float)dg - 1.0f + EPSF);
}

// ------- warp-per-node register bitonic sort (32/64-wide adaptive); 128B-row offsets -------
__global__ void k_sortu() {
    int lane = threadIdx.x & 31;
    int n = (blockIdx.x * blockDim.x + threadIdx.x) >> 5;
    if (n >= NN) return;
    int dg = g_deg[n];
    const size_t base = (size_t)n * MAXD;

    float u0 = 0.f, u1 = 0.f;

    if (dg <= 32) {
        int v0 = (lane < dg) ? g_csr[base + lane] : IMAX;
#pragma unroll
        for (int k = 2; k <= 32; k <<= 1) {
#pragma unroll
            for (int j = k >> 1; j > 0; j >>= 1) {
                int p = __shfl_xor_sync(0xffffffffu, v0, j);
                bool up = ((lane & j) == 0);
                bool dir = ((lane & k) == 0) || (k == 32);
                v0 = (up == dir) ? min(v0, p) : max(v0, p);
            }
        }
        if (lane < dg) {
            u0 = __ldg(&g_u[v0]);
            g_csr[base + lane] = v0 << 7;     // 128B fp16 rows
            g_uS[base + lane] = u0;
        }
    } else {
        int v0 = (lane < dg) ? g_csr[base + lane] : IMAX;
        int v1 = (lane + 32 < dg) ? g_csr[base + lane + 32] : IMAX;
#pragma unroll
        for (int k = 2; k <= 64; k <<= 1) {
#pragma unroll
            for (int j = k >> 1; j > 0; j >>= 1) {
                if (j == 32) {
                    bool dir = ((lane & k) == 0) || (k == 64);
                    int lo = min(v0, v1), hi = max(v0, v1);
                    v0 = dir ? lo : hi;
                    v1 = dir ? hi : lo;
                } else {
                    int p0 = __shfl_xor_sync(0xffffffffu, v0, j);
                    bool up0 = ((lane & j) == 0);
                    bool dir0 = ((lane & k) == 0) || (k == 64);
                    v0 = (up0 == dir0) ? min(v0, p0) : max(v0, p0);
                    int p1 = __shfl_xor_sync(0xffffffffu, v1, j);
                    int idx1 = lane + 32;
                    bool up1 = ((idx1 & j) == 0);
                    bool dir1 = ((idx1 & k) == 0) || (k == 64);
                    v1 = (up1 == dir1) ? min(v1, p1) : max(v1, p1);
                }
            }
        }
        if (lane < dg) {
            u0 = __ldg(&g_u[v0]);
            g_csr[base + lane] = v0 << 7;
            g_uS[base + lane] = u0;
        }
        if (lane + 32 < dg) {
            u1 = __ldg(&g_u[v1]);
            g_csr[base + lane + 32] = v1 << 7;
            g_uS[base + lane + 32] = u1;
        }
    }
    // pad 3 sentinel slots (dg <= ~45, MAXD=96: always in-bounds)
    if (lane < 3) {
        g_csr[base + dg + lane] = NN << 7;
        g_uS[base + dg + lane] = 0.f;
    }
    float suL = u0 + u1;
    float su2L = u0 * u0 + u1 * u1;
    for (int o = 16; o > 0; o >>= 1) {
        suL += __shfl_xor_sync(0xffffffffu, suL, o);
        su2L += __shfl_xor_sync(0xffffffffu, su2L, o);
    }
    if (lane == 0) { g_Su[n] = suL; g_Su2[n] = su2L; }
}

// ======== aggregation passes: warp/node, 4 neighbors/iter from fp16 rows ========
#define PASS_PROLOG                                                     \
    __shared__ int sI[8][MAXD];                                         \
    int w = threadIdx.x >> 5;                                           \
    int lane = threadIdx.x & 31;                                        \
    int n = (blockIdx.x * blockDim.x + threadIdx.x) >> 5;               \
    if (n >= NN) return;                                                \
    int dg = g_deg[n];                                                  \
    int dgp = (dg + 3) & ~3;                                            \
    const size_t base = (size_t)n * MAXD;                               \
    int grp = lane >> 3, li = lane & 7;

__global__ void k_pass1(const float* __restrict__ lm) {
    PASS_PROLOG
    __shared__ float sU[8][MAXD];
    for (int i = lane; i < dgp; i += 32) {
        sI[w][i] = g_csr[base + i];
        sU[w][i] = g_uS[base + i];
    }
    __syncwarp();
    const char* hb = (const char*)g_h16 + li * 16;
    float m0[8] = {0, 0, 0, 0, 0, 0, 0, 0};
    float sh[8] = {0, 0, 0, 0, 0, 0, 0, 0};
#pragma unroll 2
    for (int it = grp; it < dgp; it += 4) {
        int off = sI[w][it];
        float us = sU[w][it];
        uint4 raw = *(const uint4*)(hb + off);
        float2 f0 = __half22float2(*(const __half2*)&raw.x);
        float2 f1 = __half22float2(*(const __half2*)&raw.y);
        float2 f2 = __half22float2(*(const __half2*)&raw.z);
        float2 f3 = __half22float2(*(const __half2*)&raw.w);
        m0[0] += f0.x; m0[1] += f0.y; m0[2] += f1.x; m0[3] += f1.y;
        m0[4] += f2.x; m0[5] += f2.y; m0[6] += f3.x; m0[7] += f3.y;
        sh[0] = fmaf(us, f0.x, sh[0]); sh[1] = fmaf(us, f0.y, sh[1]);
        sh[2] = fmaf(us, f1.x, sh[2]); sh[3] = fmaf(us, f1.y, sh[3]);
        sh[4] = fmaf(us, f2.x, sh[4]); sh[5] = fmaf(us, f2.y, sh[5]);
        sh[6] = fmaf(us, f3.x, sh[6]); sh[7] = fmaf(us, f3.y, sh[7]);
    }
#pragma unroll
    for (int k = 0; k < 8; k++) {
        m0[k] += __shfl_xor_sync(0xffffffffu, m0[k], 8);
        m0[k] += __shfl_xor_sync(0xffffffffu, m0[k], 16);
        sh[k] += __shfl_xor_sync(0xffffffffu, sh[k], 8);
        sh[k] += __shfl_xor_sync(0xffffffffu, sh[k], 16);
    }
    if (lane < 8) {
        float lam = lm[0];
        float ud = g_u[n];
        const float* hr = g_h + (size_t)n * D + lane * 8;
        float4 h0 = *(const float4*)hr;
        float4 h1 = *(const float4*)(hr + 4);
        float hd[8] = {h0.x, h0.y, h0.z, h0.w, h1.x, h1.y, h1.z, h1.w};
        float a1[8];
#pragma unroll
        for (int k = 0; k < 8; k++)
            a1[k] = (dg == 1) ? hd[k] : (1.f - lam) * hd[k] + ud * m0[k];
        float* o1 = g_A1 + (size_t)n * D + lane * 8;
        *(float4*)o1 = make_float4(a1[0], a1[1], a1[2], a1[3]);
        *(float4*)(o1 + 4) = make_float4(a1[4], a1[5], a1[6], a1[7]);
        float* o2 = g_Suh + (size_t)n * D + lane * 8;
        *(float4*)o2 = make_float4(sh[0], sh[1], sh[2], sh[3]);
        *(float4*)(o2 + 4) = make_float4(sh[4], sh[5], sh[6], sh[7]);
        store8h(g_A116 + (size_t)n * D + lane * 8, a1);
    }
}

__global__ void k_pass2(const float* __restrict__ lm) {
    PASS_PROLOG
    __shared__ float sU[8][MAXD];
    for (int i = lane; i < dgp; i += 32) {
        sI[w][i] = g_csr[base + i];
        sU[w][i] = g_uS[base + i];
    }
    __syncwarp();
    const char* ab = (const char*)g_A116 + li * 16;
    float sa[8] = {0, 0, 0, 0, 0, 0, 0, 0};
    float sua[8] = {0, 0, 0, 0, 0, 0, 0, 0};
#pragma unroll 2
    for (int it = grp; it < dgp; it += 4) {
        int off = sI[w][it];
        float us = sU[w][it];
        uint4 raw = *(const uint4*)(ab + off);
        float2 f0 = __half22float2(*(const __half2*)&raw.x);
        float2 f1 = __half22float2(*(const __half2*)&raw.y);
        float2 f2 = __half22float2(*(const __half2*)&raw.z);
        float2 f3 = __half22float2(*(const __half2*)&raw.w);
        sa[0] += f0.x; sa[1] += f0.y; sa[2] += f1.x; sa[3] += f1.y;
        sa[4] += f2.x; sa[5] += f2.y; sa[6] += f3.x; sa[7] += f3.y;
        sua[0] = fmaf(us, f0.x, sua[0]); sua[1] = fmaf(us, f0.y, sua[1]);
        sua[2] = fmaf(us, f1.x, sua[2]); sua[3] = fmaf(us, f1.y, sua[3]);
        sua[4] = fmaf(us, f2.x, sua[4]); sua[5] = fmaf(us, f2.y, sua[5]);
        sua[6] = fmaf(us, f3.x, sua[6]); sua[7] = fmaf(us, f3.y, sua[7]);
    }
#pragma unroll
    for (int k = 0; k < 8; k++) {
        sa[k] += __shfl_xor_sync(0xffffffffu, sa[k], 8);
        sa[k] += __shfl_xor_sync(0xffffffffu, sa[k], 16);
        sua[k] += __shfl_xor_sync(0xffffffffu, sua[k], 8);
        sua[k] += __shfl_xor_sync(0xffffffffu, sua[k], 16);
    }
    if (lane < 8) {
        float lam = lm[0];
        float su = g_Su[n];
        float ud = g_u[n];
        const float* hr = g_h + (size_t)n * D + lane * 8;
        float4 h0 = *(const float4*)hr;
        float4 h1 = *(const float4*)(hr + 4);
        float hd[8] = {h0.x, h0.y, h0.z, h0.w, h1.x, h1.y, h1.z, h1.w};
        float a2[8];
#pragma unroll
        for (int k = 0; k < 8; k++)
            a2[k] = (dg == 1) ? hd[k]
                  : (1.f - lam) * hd[k] + ud * (sa[k] - su * hd[k]);
        float* o1 = g_A2 + (size_t)n * D + lane * 8;
        *(float4*)o1 = make_float4(a2[0], a2[1], a2[2], a2[3]);
        *(float4*)(o1 + 4) = make_float4(a2[4], a2[5], a2[6], a2[7]);
        float* o2 = g_SuA1 + (size_t)n * D + lane * 8;
        *(float4*)o2 = make_float4(sua[0], sua[1], sua[2], sua[3]);
        *(float4*)(o2 + 4) = make_float4(sua[4], sua[5], sua[6], sua[7]);
        store8h(g_A216 + (size_t)n * D + lane * 8, a2);
    }
}

__global__ void k_pass3(const float* __restrict__ lm) {
    PASS_PROLOG
    for (int i = lane; i < dgp; i += 32) sI[w][i] = g_csr[base + i];
    __syncwarp();
    const char* ab = (const char*)g_A216 + li * 16;
    float sa[8] = {0, 0, 0, 0, 0, 0, 0, 0};
#pragma unroll 2
    for (int it = grp; it < dgp; it += 4) {
        int off = sI[w][it];
        uint4 raw = *(const uint4*)(ab + off);
        float2 f0 = __half22float2(*(const __half2*)&raw.x);
        float2 f1 = __half22float2(*(const __half2*)&raw.y);
        float2 f2 = __half22float2(*(const __half2*)&raw.z);
        float2 f3 = __half22float2(*(const __half2*)&raw.w);
        sa[0] += f0.x; sa[1] += f0.y; sa[2] += f1.x; sa[3] += f1.y;
        sa[4] += f2.x; sa[5] += f2.y; sa[6] += f3.x; sa[7] += f3.y;
    }
#pragma unroll
    for (int k = 0; k < 8; k++) {
        sa[k] += __shfl_xor_sync(0xffffffffu, sa[k], 8);
        sa[k] += __shfl_xor_sync(0xffffffffu, sa[k], 16);
    }
    if (lane < 8) {
        float lam = lm[0];
        float su = g_Su[n];
        float ud = g_u[n];
        const float* hr = g_h + (size_t)n * D + lane * 8;
        const float* a1r = g_A1 + (size_t)n * D + lane * 8;
        const float* shr = g_Suh + (size_t)n * D + lane * 8;
        float4 h0 = *(const float4*)hr,  h1 = *(const float4*)(hr + 4);
        float4 a0 = *(const float4*)a1r, a1v = *(const float4*)(a1r + 4);
        float4 s0 = *(const float4*)shr, s1 = *(const float4*)(shr + 4);
        float hd[8]  = {h0.x, h0.y, h0.z, h0.w, h1.x, h1.y, h1.z, h1.w};
        float a1d[8] = {a0.x, a0.y, a0.z, a0.w, a1v.x, a1v.y, a1v.z, a1v.w};
        float sh[8]  = {s0.x, s0.y, s0.z, s0.w, s1.x, s1.y, s1.z, s1.w};
        float a3[8];
#pragma unroll
        for (int k = 0; k < 8; k++)
            a3[k] = (dg == 1) ? hd[k]
                  : (1.f - lam) * hd[k] + ud * (sa[k] - su * a1d[k] + ud * sh[k]);
        store8h(g_A316 + (size_t)n * D + lane * 8, a3);
    }
}

__global__ void k_pass4(const float* __restrict__ lm, const float* __restrict__ x,
                        float* __restrict__ out) {
    PASS_PROLOG
    for (int i = lane; i < dgp; i += 32) sI[w][i] = g_csr[base + i];
    __syncwarp();
    const char* ab = (const char*)g_A316 + li * 16;
    float sa[8] = {0, 0, 0, 0, 0, 0, 0, 0};
#pragma unroll 2
    for (int it = grp; it < dgp; it += 4) {
        int off = sI[w][it];
        uint4 raw = *(const uint4*)(ab + off);
        float2 f0 = __half22float2(*(const __half2*)&raw.x);
        float2 f1 = __half22float2(*(const __half2*)&raw.y);
        float2 f2 = __half22float2(*(const __half2*)&raw.z);
        float2 f3 = __half22float2(*(const __half2*)&raw.w);
        sa[0] += f0.x; sa[1] += f0.y; sa[2] += f1.x; sa[3] += f1.y;
        sa[4] += f2.x; sa[5] += f2.y; sa[6] += f3.x; sa[7] += f3.y;
    }
#pragma unroll
    for (int k = 0; k < 8; k++) {
        sa[k] += __shfl_xor_sync(0xffffffffu, sa[k], 8);
        sa[k] += __shfl_xor_sync(0xffffffffu, sa[k], 16);
    }
    if (lane < 8) {
        float lam = lm[0];
        float su = g_Su[n];
        float su2 = g_Su2[n];
        float ud = g_u[n];
        const float* hr = g_h + (size_t)n * D + lane * 8;
        const float* a2r = g_A2 + (size_t)n * D + lane * 8;
        const float* sar = g_SuA1 + (size_t)n * D + lane * 8;
        const float* xr = x + (size_t)n * D + lane * 8;
        float4 h0 = *(const float4*)hr,  h1 = *(const float4*)(hr + 4);
        float4 b0 = *(const float4*)a2r, b1 = *(const float4*)(a2r + 4);
        float4 c0 = *(const float4*)sar, c1 = *(const float4*)(sar + 4);
        float4 x0 = *(const float4*)xr,  x1 = *(const float4*)(xr + 4);
        float hd[8]   = {h0.x, h0.y, h0.z, h0.w, h1.x, h1.y, h1.z, h1.w};
        float a2d[8]  = {b0.x, b0.y, b0.z, b0.w, b1.x, b1.y, b1.z, b1.w};
        float sua[8]  = {c0.x, c0.y, c0.z, c0.w, c1.x, c1.y, c1.z, c1.w};
        float xd[8]   = {x0.x, x0.y, x0.z, x0.w, x1.x, x1.y, x1.z, x1.w};
        float o[8];
        float c = lam / ((float)dg + EPSF);
        float us2 = ud * su2;
#pragma unroll
        for (int k = 0; k < 8; k++) {
            float tmp;
            if (dg == 0) tmp = hd[k];
            else tmp = (1.f - lam) * hd[k]
                     + c * (sa[k] - su * a2d[k] + ud * sua[k] - us2 * hd[k]);
            o[k] = xd[k] + fmaxf(tmp, 0.f);
        }
        float* op = out + (size_t)n * D + lane * 8;
        *(float4*)op = make_float4(o[0], o[1], o[2], o[3]);
        *(float4*)(op + 4) = make_float4(o[4], o[5], o[6], o[7]);
    }
}

extern "C" void kernel_launch(void* const* d_in, const int* in_sizes, int n_in,
                              void* d_out, int out_size) {
    const float* x = (const float*)d_in[0];
    const int* edge_index = (const int*)d_in[1];
    const float* W = (const float*)d_in[2];
    const float* b = (const float*)d_in[3];
    const float* lm = (const float*)d_in[4];
    float* out = (float*)d_out;

    const int* src = edge_index;        // row 0
    const int* dst = edge_index + EE;   // row 1

    k_gemm<<<(NN + 127) / 128, 128>>>(x, W, b);
    k_fill<<<(EE + 255) / 256, 256>>>(src, dst);
    k_u<<<(NN + 255) / 256, 256>>>(lm);
    int wblocks = (NN * 32 + 255) / 256;
    k_sortu<<<wblocks, 256>>>();
    k_pass1<<<wblocks, 256>>>(lm);
    k_pass2<<<wblocks, 256>>>(lm);
    k_pass3<<<wblocks, 256>>>(lm);
    k_pass4<<<wblocks, 256>>>(lm, x, out);
}

// round 12
// speedup vs baseline: 1.3786x; 1.3786x over previous
#include <cuda_runtime.h>
#include <cuda_bf16.h>
#include <cstdint>

#define NN 100000
#define EE 1600000
#define D 64
#define MAXD 96
#define EPSF 1e-9f
#define IMAX 0x7fffffff

// ---- static device scratch (no allocation allowed) ----
// f32 arrays: epilogue own-row reads/writes. bf16 mirrors: gathered (row NN = zero sentinel).
__device__ float g_h[(NN + 1) * D];
__device__ float g_A1[(NN + 1) * D];
__device__ float g_A2[(NN + 1) * D];
__device__ float g_Suh[NN * D];
__device__ float g_SuA1[NN * D];
__device__ __nv_bfloat16 g_h16[(NN + 1) * D];
__device__ __nv_bfloat16 g_A116[(NN + 1) * D];
__device__ __nv_bfloat16 g_A216[(NN + 1) * D];
__device__ __nv_bfloat16 g_A316[(NN + 1) * D];
__device__ int   g_deg[NN];
__device__ int   g_cursor[NN];
__device__ float g_u[NN + 1];
__device__ float g_Su[NN];
__device__ float g_Su2[NN];
__device__ int   g_csr[(size_t)NN * MAXD];   // byte offsets (s * 128) after sortu
__device__ float g_uS[(size_t)NN * MAXD];    // u values aligned with sorted csr

__device__ __forceinline__ void store8bf(__nv_bfloat16* p, const float* v) {
    __nv_bfloat162 h0 = __floats2bfloat162_rn(v[0], v[1]);  // .x = lo = v[0]
    __nv_bfloat162 h1 = __floats2bfloat162_rn(v[2], v[3]);
    __nv_bfloat162 h2 = __floats2bfloat162_rn(v[4], v[5]);
    __nv_bfloat162 h3 = __floats2bfloat162_rn(v[6], v[7]);
    uint4 r;
    r.x = *(unsigned int*)&h0; r.y = *(unsigned int*)&h1;
    r.z = *(unsigned int*)&h2; r.w = *(unsigned int*)&h3;
    *(uint4*)p = r;
}

// unpack packed bf16 pair -> two f32 (pure ALU: SHF + LOP3)
#define BF2LO(p) __uint_as_float((p) << 16)
#define BF2HI(p) __uint_as_float((p) & 0xFFFF0000u)

// ---------------- h = x @ W + b  (f32 + bf16; zero cursor + sentinels) ----------------
__global__ void k_gemm(const float* __restrict__ x, const float* __restrict__ W,
                       const float* __restrict__ b) {
    __shared__ float Ws[D * D];
    __shared__ float bs[D];
    for (int i = threadIdx.x; i < D * D; i += blockDim.x) Ws[i] = W[i];
    if (threadIdx.x < D) bs[threadIdx.x] = b[threadIdx.x];
    __syncthreads();
    int row = blockIdx.x * blockDim.x + threadIdx.x;
    if (blockIdx.x == 0 && threadIdx.x < D) {
        g_h[NN * D + threadIdx.x] = 0.f;
        g_h16[NN * D + threadIdx.x] = __float2bfloat16(0.f);
        g_A116[NN * D + threadIdx.x] = __float2bfloat16(0.f);
        g_A216[NN * D + threadIdx.x] = __float2bfloat16(0.f);
        g_A316[NN * D + threadIdx.x] = __float2bfloat16(0.f);
        if (threadIdx.x == 0) g_u[NN] = 0.f;
    }
    if (row >= NN) return;
    g_cursor[row] = 0;
    float acc[D];
#pragma unroll
    for (int j = 0; j < D; j++) acc[j] = bs[j];
    const float4* xr = (const float4*)(x + (size_t)row * D);
#pragma unroll 2
    for (int k4 = 0; k4 < 16; k4++) {
        float4 xv = xr[k4];
#pragma unroll
        for (int kk = 0; kk < 4; kk++) {
            float xk = (kk == 0) ? xv.x : (kk == 1) ? xv.y : (kk == 2) ? xv.z : xv.w;
            const float4* wr = (const float4*)&Ws[(k4 * 4 + kk) * D];
#pragma unroll
            for (int j4 = 0; j4 < 16; j4++) {
                float4 w = wr[j4];
                acc[j4 * 4 + 0] += xk * w.x;
                acc[j4 * 4 + 1] += xk * w.y;
                acc[j4 * 4 + 2] += xk * w.z;
                acc[j4 * 4 + 3] += xk * w.w;
            }
        }
    }
    float4* hr = (float4*)(g_h + (size_t)row * D);
#pragma unroll
    for (int j4 = 0; j4 < 16; j4++)
        hr[j4] = make_float4(acc[j4 * 4], acc[j4 * 4 + 1], acc[j4 * 4 + 2], acc[j4 * 4 + 3]);
#pragma unroll
    for (int j = 0; j < 8; j++)
        store8bf(g_h16 + (size_t)row * D + j * 8, acc + j * 8);
}

// ---------------- CSR fill ----------------
__global__ void k_fill(const int* __restrict__ src, const int* __restrict__ dst) {
    int e = blockIdx.x * blockDim.x + threadIdx.x;
    if (e >= EE) return;
    int d = dst[e];
    int pos = atomicAdd(&g_cursor[d], 1);
    if (pos < MAXD) g_csr[(size_t)d * MAXD + pos] = src[e];
}

// ---------------- per-node u + deg ----------------
__global__ void k_u(const float* __restrict__ lm) {
    int i = blockIdx.x * blockDim.x + threadIdx.x;
    if (i >= NN) return;
    int dg = min(g_cursor[i], MAXD);
    g_deg[i] = dg;
    g_u[i] = (dg <= 1) ? 0.f : lm[0] / ((float)dg - 1.0f + EPSF);
}

// ------- warp-per-node register bitonic sort (32/64-wide adaptive); 128B-row offsets -------
__global__ void k_sortu() {
    int lane = threadIdx.x & 31;
    int n = (blockIdx.x * blockDim.x + threadIdx.x) >> 5;
    if (n >= NN) return;
    int dg = g_deg[n];
    const size_t base = (size_t)n * MAXD;

    float u0 = 0.f, u1 = 0.f;

    if (dg <= 32) {
        int v0 = (lane < dg) ? g_csr[base + lane] : IMAX;
#pragma unroll
        for (int k = 2; k <= 32; k <<= 1) {
#pragma unroll
            for (int j = k >> 1; j > 0; j >>= 1) {
                int p = __shfl_xor_sync(0xffffffffu, v0, j);
                bool up = ((lane & j) == 0);
                bool dir = ((lane & k) == 0) || (k == 32);
                v0 = (up == dir) ? min(v0, p) : max(v0, p);
            }
        }
        if (lane < dg) {
            u0 = __ldg(&g_u[v0]);
            g_csr[base + lane] = v0 << 7;     // 128B bf16 rows
            g_uS[base + lane] = u0;
        }
    } else {
        int v0 = (lane < dg) ? g_csr[base + lane] : IMAX;
        int v1 = (lane + 32 < dg) ? g_csr[base + lane + 32] : IMAX;
#pragma unroll
        for (int k = 2; k <= 64; k <<= 1) {
#pragma unroll
            for (int j = k >> 1; j > 0; j >>= 1) {
                if (j == 32) {
                    bool dir = ((lane & k) == 0) || (k == 64);
                    int lo = min(v0, v1), hi = max(v0, v1);
                    v0 = dir ? lo : hi;
                    v1 = dir ? hi : lo;
                } else {
                    int p0 = __shfl_xor_sync(0xffffffffu, v0, j);
                    bool up0 = ((lane & j) == 0);
                    bool dir0 = ((lane & k) == 0) || (k == 64);
                    v0 = (up0 == dir0) ? min(v0, p0) : max(v0, p0);
                    int p1 = __shfl_xor_sync(0xffffffffu, v1, j);
                    int idx1 = lane + 32;
                    bool up1 = ((idx1 & j) == 0);
                    bool dir1 = ((idx1 & k) == 0) || (k == 64);
                    v1 = (up1 == dir1) ? min(v1, p1) : max(v1, p1);
                }
            }
        }
        if (lane < dg) {
            u0 = __ldg(&g_u[v0]);
            g_csr[base + lane] = v0 << 7;
            g_uS[base + lane] = u0;
        }
        if (lane + 32 < dg) {
            u1 = __ldg(&g_u[v1]);
            g_csr[base + lane + 32] = v1 << 7;
            g_uS[base + lane + 32] = u1;
        }
    }
    // pad 3 sentinel slots (dg <= ~45, MAXD=96: always in-bounds)
    if (lane < 3) {
        g_csr[base + dg + lane] = NN << 7;
        g_uS[base + dg + lane] = 0.f;
    }
    float suL = u0 + u1;
    float su2L = u0 * u0 + u1 * u1;
    for (int o = 16; o > 0; o >>= 1) {
        suL += __shfl_xor_sync(0xffffffffu, suL, o);
        su2L += __shfl_xor_sync(0xffffffffu, su2L, o);
    }
    if (lane == 0) { g_Su[n] = suL; g_Su2[n] = su2L; }
}

// ======== aggregation passes: warp/node, 4 neighbors/iter from bf16 rows ========
#define PASS_PROLOG                                                     \
    __shared__ int sI[8][MAXD];                                         \
    int w = threadIdx.x >> 5;                                           \
    int lane = threadIdx.x & 31;                                        \
    int n = (blockIdx.x * blockDim.x + threadIdx.x) >> 5;               \
    if (n >= NN) return;                                                \
    int dg = g_deg[n];                                                  \
    int dgp = (dg + 3) & ~3;                                            \
    const size_t base = (size_t)n * MAXD;                               \
    int grp = lane >> 3, li = lane & 7;

__global__ void k_pass1(const float* __restrict__ lm) {
    PASS_PROLOG
    __shared__ float sU[8][MAXD];
    for (int i = lane; i < dgp; i += 32) {
        sI[w][i] = g_csr[base + i];
        sU[w][i] = g_uS[base + i];
    }
    __syncwarp();
    const char* hb = (const char*)g_h16 + li * 16;
    float m0[8] = {0, 0, 0, 0, 0, 0, 0, 0};
    float sh[8] = {0, 0, 0, 0, 0, 0, 0, 0};
#pragma unroll 2
    for (int it = grp; it < dgp; it += 4) {
        int off = sI[w][it];
        float us = sU[w][it];
        uint4 raw = *(const uint4*)(hb + off);
        float f0 = BF2LO(raw.x), f1 = BF2HI(raw.x);
        float f2 = BF2LO(raw.y), f3 = BF2HI(raw.y);
        float f4 = BF2LO(raw.z), f5 = BF2HI(raw.z);
        float f6 = BF2LO(raw.w), f7 = BF2HI(raw.w);
        m0[0] += f0; m0[1] += f1; m0[2] += f2; m0[3] += f3;
        m0[4] += f4; m0[5] += f5; m0[6] += f6; m0[7] += f7;
        sh[0] = fmaf(us, f0, sh[0]); sh[1] = fmaf(us, f1, sh[1]);
        sh[2] = fmaf(us, f2, sh[2]); sh[3] = fmaf(us, f3, sh[3]);
        sh[4] = fmaf(us, f4, sh[4]); sh[5] = fmaf(us, f5, sh[5]);
        sh[6] = fmaf(us, f6, sh[6]); sh[7] = fmaf(us, f7, sh[7]);
    }
#pragma unroll
    for (int k = 0; k < 8; k++) {
        m0[k] += __shfl_xor_sync(0xffffffffu, m0[k], 8);
        m0[k] += __shfl_xor_sync(0xffffffffu, m0[k], 16);
        sh[k] += __shfl_xor_sync(0xffffffffu, sh[k], 8);
        sh[k] += __shfl_xor_sync(0xffffffffu, sh[k], 16);
    }
    if (lane < 8) {
        float lam = lm[0];
        float ud = g_u[n];
        const float* hr = g_h + (size_t)n * D + lane * 8;
        float4 h0 = *(const float4*)hr;
        float4 h1 = *(const float4*)(hr + 4);
        float hd[8] = {h0.x, h0.y, h0.z, h0.w, h1.x, h1.y, h1.z, h1.w};
        float a1[8];
#pragma unroll
        for (int k = 0; k < 8; k++)
            a1[k] = (dg == 1) ? hd[k] : (1.f - lam) * hd[k] + ud * m0[k];
        float* o1 = g_A1 + (size_t)n * D + lane * 8;
        *(float4*)o1 = make_float4(a1[0], a1[1], a1[2], a1[3]);
        *(float4*)(o1 + 4) = make_float4(a1[4], a1[5], a1[6], a1[7]);
        float* o2 = g_Suh + (size_t)n * D + lane * 8;
        *(float4*)o2 = make_float4(sh[0], sh[1], sh[2], sh[3]);
        *(float4*)(o2 + 4) = make_float4(sh[4], sh[5], sh[6], sh[7]);
        store8bf(g_A116 + (size_t)n * D + lane * 8, a1);
    }
}

__global__ void k_pass2(const float* __restrict__ lm) {
    PASS_PROLOG
    __shared__ float sU[8][MAXD];
    for (int i = lane; i < dgp; i += 32) {
        sI[w][i] = g_csr[base + i];
        sU[w][i] = g_uS[base + i];
    }
    __syncwarp();
    const char* ab = (const char*)g_A116 + li * 16;
    float sa[8] = {0, 0, 0, 0, 0, 0, 0, 0};
    float sua[8] = {0, 0, 0, 0, 0, 0, 0, 0};
#pragma unroll 2
    for (int it = grp; it < dgp; it += 4) {
        int off = sI[w][it];
        float us = sU[w][it];
        uint4 raw = *(const uint4*)(ab + off);
        float f0 = BF2LO(raw.x), f1 = BF2HI(raw.x);
        float f2 = BF2LO(raw.y), f3 = BF2HI(raw.y);
        float f4 = BF2LO(raw.z), f5 = BF2HI(raw.z);
        float f6 = BF2LO(raw.w), f7 = BF2HI(raw.w);
        sa[0] += f0; sa[1] += f1; sa[2] += f2; sa[3] += f3;
        sa[4] += f4; sa[5] += f5; sa[6] += f6; sa[7] += f7;
        sua[0] = fmaf(us, f0, sua[0]); sua[1] = fmaf(us, f1, sua[1]);
        sua[2] = fmaf(us, f2, sua[2]); sua[3] = fmaf(us, f3, sua[3]);
        sua[4] = fmaf(us, f4, sua[4]); sua[5] = fmaf(us, f5, sua[5]);
        sua[6] = fmaf(us, f6, sua[6]); sua[7] = fmaf(us, f7, sua[7]);
    }
#pragma unroll
    for (int k = 0; k < 8; k++) {
        sa[k] += __shfl_xor_sync(0xffffffffu, sa[k], 8);
        sa[k] += __shfl_xor_sync(0xffffffffu, sa[k], 16);
        sua[k] += __shfl_xor_sync(0xffffffffu, sua[k], 8);
        sua[k] += __shfl_xor_sync(0xffffffffu, sua[k], 16);
    }
    if (lane < 8) {
        float lam = lm[0];
        float su = g_Su[n];
        float ud = g_u[n];
        const float* hr = g_h + (size_t)n * D + lane * 8;
        float4 h0 = *(const float4*)hr;
        float4 h1 = *(const float4*)(hr + 4);
        float hd[8] = {h0.x, h0.y, h0.z, h0.w, h1.x, h1.y, h1.z, h1.w};
        float a2[8];
#pragma unroll
        for (int k = 0; k < 8; k++)
            a2[k] = (dg == 1) ? hd[k]
                  : (1.f - lam) * hd[k] + ud * (sa[k] - su * hd[k]);
        float* o1 = g_A2 + (size_t)n * D + lane * 8;
        *(float4*)o1 = make_float4(a2[0], a2[1], a2[2], a2[3]);
        *(float4*)(o1 + 4) = make_float4(a2[4], a2[5], a2[6], a2[7]);
        float* o2 = g_SuA1 + (size_t)n * D + lane * 8;
        *(float4*)o2 = make_float4(sua[0], sua[1], sua[2], sua[3]);
        *(float4*)(o2 + 4) = make_float4(sua[4], sua[5], sua[6], sua[7]);
        store8bf(g_A216 + (size_t)n * D + lane * 8, a2);
    }
}

__global__ void k_pass3(const float* __restrict__ lm) {
    PASS_PROLOG
    for (int i = lane; i < dgp; i += 32) sI[w][i] = g_csr[base + i];
    __syncwarp();
    const char* ab = (const char*)g_A216 + li * 16;
    float sa[8] = {0, 0, 0, 0, 0, 0, 0, 0};
#pragma unroll 2
    for (int it = grp; it < dgp; it += 4) {
        int off = sI[w][it];
        uint4 raw = *(const uint4*)(ab + off);
        sa[0] += BF2LO(raw.x); sa[1] += BF2HI(raw.x);
        sa[2] += BF2LO(raw.y); sa[3] += BF2HI(raw.y);
        sa[4] += BF2LO(raw.z); sa[5] += BF2HI(raw.z);
        sa[6] += BF2LO(raw.w); sa[7] += BF2HI(raw.w);
    }
#pragma unroll
    for (int k = 0; k < 8; k++) {
        sa[k] += __shfl_xor_sync(0xffffffffu, sa[k], 8);
        sa[k] += __shfl_xor_sync(0xffffffffu, sa[k], 16);
    }
    if (lane < 8) {
        float lam = lm[0];
        float su = g_Su[n];
        float ud = g_u[n];
        const float* hr = g_h + (size_t)n * D + lane * 8;
        const float* a1r = g_A1 + (size_t)n * D + lane * 8;
        const float* shr = g_Suh + (size_t)n * D + lane * 8;
        float4 h0 = *(const float4*)hr,  h1 = *(const float4*)(hr + 4);
        float4 a0 = *(const float4*)a1r, a1v = *(const float4*)(a1r + 4);
        float4 s0 = *(const float4*)shr, s1 = *(const float4*)(shr + 4);
        float hd[8]  = {h0.x, h0.y, h0.z, h0.w, h1.x, h1.y, h1.z, h1.w};
        float a1d[8] = {a0.x, a0.y, a0.z, a0.w, a1v.x, a1v.y, a1v.z, a1v.w};
        float sh[8]  = {s0.x, s0.y, s0.z, s0.w, s1.x, s1.y, s1.z, s1.w};
        float a3[8];
#pragma unroll
        for (int k = 0; k < 8; k++)
            a3[k] = (dg == 1) ? hd[k]
                  : (1.f - lam) * hd[k] + ud * (sa[k] - su * a1d[k] + ud * sh[k]);
        store8bf(g_A316 + (size_t)n * D + lane * 8, a3);
    }
}

__global__ void k_pass4(const float* __restrict__ lm, const float* __restrict__ x,
                        float* __restrict__ out) {
    PASS_PROLOG
    for (int i = lane; i < dgp; i += 32) sI[w][i] = g_csr[base + i];
    __syncwarp();
    const char* ab = (const char*)g_A316 + li * 16;
    float sa[8] = {0, 0, 0, 0, 0, 0, 0, 0};
#pragma unroll 2
    for (int it = grp; it < dgp; it += 4) {
        int off = sI[w][it];
        uint4 raw = *(const uint4*)(ab + off);
        sa[0] += BF2LO(raw.x); sa[1] += BF2HI(raw.x);
        sa[2] += BF2LO(raw.y); sa[3] += BF2HI(raw.y);
        sa[4] += BF2LO(raw.z); sa[5] += BF2HI(raw.z);
        sa[6] += BF2LO(raw.w); sa[7] += BF2HI(raw.w);
    }
#pragma unroll
    for (int k = 0; k < 8; k++) {
        sa[k] += __shfl_xor_sync(0xffffffffu, sa[k], 8);
        sa[k] += __shfl_xor_sync(0xffffffffu, sa[k], 16);
    }
    if (lane < 8) {
        float lam = lm[0];
        float su = g_Su[n];
        float su2 = g_Su2[n];
        float ud = g_u[n];
        const float* hr = g_h + (size_t)n * D + lane * 8;
        const float* a2r = g_A2 + (size_t)n * D + lane * 8;
        const float* sar = g_SuA1 + (size_t)n * D + lane * 8;
        const float* xr = x + (size_t)n * D + lane * 8;
        float4 h0 = *(const float4*)hr,  h1 = *(const float4*)(hr + 4);
        float4 b0 = *(const float4*)a2r, b1 = *(const float4*)(a2r + 4);
        float4 c0 = *(const float4*)sar, c1 = *(const float4*)(sar + 4);
        float4 x0 = *(const float4*)xr,  x1 = *(const float4*)(xr + 4);
        float hd[8]   = {h0.x, h0.y, h0.z, h0.w, h1.x, h1.y, h1.z, h1.w};
        float a2d[8]  = {b0.x, b0.y, b0.z, b0.w, b1.x, b1.y, b1.z, b1.w};
        float sua[8]  = {c0.x, c0.y, c0.z, c0.w, c1.x, c1.y, c1.z, c1.w};
        float xd[8]   = {x0.x, x0.y, x0.z, x0.w, x1.x, x1.y, x1.z, x1.w};
        float o[8];
        float c = lam / ((float)dg + EPSF);
        float us2 = ud * su2;
#pragma unroll
        for (int k = 0; k < 8; k++) {
            float tmp;
            if (dg == 0) tmp = hd[k];
            else tmp = (1.f - lam) * hd[k]
                     + c * (sa[k] - su * a2d[k] + ud * sua[k] - us2 * hd[k]);
            o[k] = xd[k] + fmaxf(tmp, 0.f);
        }
        float* op = out + (size_t)n * D + lane * 8;
        *(float4*)op = make_float4(o[0], o[1], o[2], o[3]);
        *(float4*)(op + 4) = make_float4(o[4], o[5], o[6], o[7]);
    }
}

extern "C" void kernel_launch(void* const* d_in, const int* in_sizes, int n_in,
                              void* d_out, int out_size) {
    const float* x = (const float*)d_in[0];
    const int* edge_index = (const int*)d_in[1];
    const float* W = (const float*)d_in[2];
    const float* b = (const float*)d_in[3];
    const float* lm = (const float*)d_in[4];
    float* out = (float*)d_out;

    const int* src = edge_index;        // row 0
    const int* dst = edge_index + EE;   // row 1

    k_gemm<<<(NN + 127) / 128, 128>>>(x, W, b);
    k_fill<<<(EE + 255) / 256, 256>>>(src, dst);
    k_u<<<(NN + 255) / 256, 256>>>(lm);
    int wblocks = (NN * 32 + 255) / 256;
    k_sortu<<<wblocks, 256>>>();
    k_pass1<<<wblocks, 256>>>(lm);
    k_pass2<<<wblocks, 256>>>(lm);
    k_pass3<<<wblocks, 256>>>(lm);
    k_pass4<<<wblocks, 256>>>(lm, x, out);
}

// round 13
// speedup vs baseline: 1.5685x; 1.1378x over previous
#include <cuda_runtime.h>
#include <cstdint>

#define NN 100000
#define EE 1600000
#define D 64
#define MAXD 96
#define EPSF 1e-9f
#define IMAX 0x7fffffff

// ---- static device scratch (no allocation allowed) ----
// feature arrays have NN+1 rows; row NN is an all-zero sentinel
__device__ float g_h[(NN + 1) * D];
__device__ float g_A1[(NN + 1) * D];
__device__ float g_A2[(NN + 1) * D];
__device__ float g_A3[(NN + 1) * D];
__device__ float g_Suh[NN * D];
__device__ float g_SuA1[NN * D];
__device__ int   g_deg[NN];
__device__ int   g_cursor[NN];
__device__ float g_Su[NN];
__device__ float g_Su2[NN];
__device__ int   g_csr[(size_t)NN * MAXD];   // byte offsets (s * 256) after sortu
__device__ float g_uS[(size_t)NN * MAXD];    // u values aligned with sorted csr

__device__ __forceinline__ float4 f4zero() { return make_float4(0.f, 0.f, 0.f, 0.f); }
__device__ __forceinline__ void f4acc(float4& a, const float4 v) {
    a.x += v.x; a.y += v.y; a.z += v.z; a.w += v.w;
}
__device__ __forceinline__ void f4fma(float4& a, float c, const float4 v) {
    a.x = fmaf(c, v.x, a.x); a.y = fmaf(c, v.y, a.y);
    a.z = fmaf(c, v.z, a.z); a.w = fmaf(c, v.w, a.w);
}
__device__ __forceinline__ void f4xor16(float4& a) {
    a.x += __shfl_xor_sync(0xffffffffu, a.x, 16);
    a.y += __shfl_xor_sync(0xffffffffu, a.y, 16);
    a.z += __shfl_xor_sync(0xffffffffu, a.z, 16);
    a.w += __shfl_xor_sync(0xffffffffu, a.w, 16);
}

__device__ __forceinline__ float u_of_deg(int dg, float lam) {
    return (dg <= 1) ? 0.f : lam / ((float)dg - 1.0f + EPSF);
}

// ---------------- h = x @ W + b  (also zeroes cursor + sentinel rows) ----------------
__global__ void k_gemm(const float* __restrict__ x, const float* __restrict__ W,
                       const float* __restrict__ b) {
    __shared__ float Ws[D * D];
    __shared__ float bs[D];
    for (int i = threadIdx.x; i < D * D; i += blockDim.x) Ws[i] = W[i];
    if (threadIdx.x < D) bs[threadIdx.x] = b[threadIdx.x];
    __syncthreads();
    int row = blockIdx.x * blockDim.x + threadIdx.x;
    if (blockIdx.x == 0 && threadIdx.x < D) {
        g_h[NN * D + threadIdx.x] = 0.f;
        g_A1[NN * D + threadIdx.x] = 0.f;
        g_A2[NN * D + threadIdx.x] = 0.f;
        g_A3[NN * D + threadIdx.x] = 0.f;
    }
    if (row >= NN) return;
    g_cursor[row] = 0;
    float acc[D];
#pragma unroll
    for (int j = 0; j < D; j++) acc[j] = bs[j];
    const float4* xr = (const float4*)(x + (size_t)row * D);
#pragma unroll 2
    for (int k4 = 0; k4 < 16; k4++) {
        float4 xv = xr[k4];
#pragma unroll
        for (int kk = 0; kk < 4; kk++) {
            float xk = (kk == 0) ? xv.x : (kk == 1) ? xv.y : (kk == 2) ? xv.z : xv.w;
            const float4* wr = (const float4*)&Ws[(k4 * 4 + kk) * D];
#pragma unroll
            for (int j4 = 0; j4 < 16; j4++) {
                float4 w = wr[j4];
                acc[j4 * 4 + 0] += xk * w.x;
                acc[j4 * 4 + 1] += xk * w.y;
                acc[j4 * 4 + 2] += xk * w.z;
                acc[j4 * 4 + 3] += xk * w.w;
            }
        }
    }
    float4* hr = (float4*)(g_h + (size_t)row * D);
#pragma unroll
    for (int j4 = 0; j4 < 16; j4++)
        hr[j4] = make_float4(acc[j4 * 4], acc[j4 * 4 + 1], acc[j4 * 4 + 2], acc[j4 * 4 + 3]);
}

// ---------------- CSR fill, 4 edges per thread via int4 ----------------
__global__ void k_fill(const int* __restrict__ src, const int* __restrict__ dst) {
    int t = blockIdx.x * blockDim.x + threadIdx.x;
    if (t >= EE / 4) return;
    int4 s4 = ((const int4*)src)[t];
    int4 d4 = ((const int4*)dst)[t];
    int pos;
    pos = atomicAdd(&g_cursor[d4.x], 1);
    if (pos < MAXD) g_csr[(size_t)d4.x * MAXD + pos] = s4.x;
    pos = atomicAdd(&g_cursor[d4.y], 1);
    if (pos < MAXD) g_csr[(size_t)d4.y * MAXD + pos] = s4.y;
    pos = atomicAdd(&g_cursor[d4.z], 1);
    if (pos < MAXD) g_csr[(size_t)d4.z * MAXD + pos] = s4.z;
    pos = atomicAdd(&g_cursor[d4.w], 1);
    if (pos < MAXD) g_csr[(size_t)d4.w * MAXD + pos] = s4.w;
}

// ------- warp-per-node register bitonic sort; u computed inline from cursor -------
__global__ void k_sortu(const float* __restrict__ lm) {
    int lane = threadIdx.x & 31;
    int n = (blockIdx.x * blockDim.x + threadIdx.x) >> 5;
    if (n >= NN) return;
    int dg = min(g_cursor[n], MAXD);
    const size_t base = (size_t)n * MAXD;
    float lam = lm[0];

    float u0 = 0.f, u1 = 0.f;

    if (dg <= 32) {
        int v0 = (lane < dg) ? g_csr[base + lane] : IMAX;
#pragma unroll
        for (int k = 2; k <= 32; k <<= 1) {
#pragma unroll
            for (int j = k >> 1; j > 0; j >>= 1) {
                int p = __shfl_xor_sync(0xffffffffu, v0, j);
                bool up = ((lane & j) == 0);
                bool dir = ((lane & k) == 0) || (k == 32);
                v0 = (up == dir) ? min(v0, p) : max(v0, p);
            }
        }
        if (lane < dg) {
            int c0 = min(__ldg(&g_cursor[v0]), MAXD);
            u0 = u_of_deg(c0, lam);
            g_csr[base + lane] = v0 << 8;     // 256B f32 rows
            g_uS[base + lane] = u0;
        }
    } else {
        int v0 = (lane < dg) ? g_csr[base + lane] : IMAX;
        int v1 = (lane + 32 < dg) ? g_csr[base + lane + 32] : IMAX;
#pragma unroll
        for (int k = 2; k <= 64; k <<= 1) {
#pragma unroll
            for (int j = k >> 1; j > 0; j >>= 1) {
                if (j == 32) {
                    bool dir = ((lane & k) == 0) || (k == 64);
                    int lo = min(v0, v1), hi = max(v0, v1);
                    v0 = dir ? lo : hi;
                    v1 = dir ? hi : lo;
                } else {
                    int p0 = __shfl_xor_sync(0xffffffffu, v0, j);
                    bool up0 = ((lane & j) == 0);
                    bool dir0 = ((lane & k) == 0) || (k == 64);
                    v0 = (up0 == dir0) ? min(v0, p0) : max(v0, p0);
                    int p1 = __shfl_xor_sync(0xffffffffu, v1, j);
                    int idx1 = lane + 32;
                    bool up1 = ((idx1 & j) == 0);
                    bool dir1 = ((idx1 & k) == 0) || (k == 64);
                    v1 = (up1 == dir1) ? min(v1, p1) : max(v1, p1);
                }
            }
        }
        if (lane < dg) {
            int c0 = min(__ldg(&g_cursor[v0]), MAXD);
            u0 = u_of_deg(c0, lam);
            g_csr[base + lane] = v0 << 8;
            g_uS[base + lane] = u0;
        }
        if (lane + 32 < dg) {
            int c1 = min(__ldg(&g_cursor[v1]), MAXD);
            u1 = u_of_deg(c1, lam);
            g_csr[base + lane + 32] = v1 << 8;
            g_uS[base + lane + 32] = u1;
        }
    }
    // pad 2 sentinel slots for the 2-neighbor loop (guarded; dg ~<= 45 << MAXD)
    if (lane < 2 && dg + lane < MAXD) {
        g_csr[base + dg + lane] = NN << 8;
        g_uS[base + dg + lane] = 0.f;
    }
    float suL = u0 + u1;
    float su2L = u0 * u0 + u1 * u1;
    for (int o = 16; o > 0; o >>= 1) {
        suL += __shfl_xor_sync(0xffffffffu, suL, o);
        su2L += __shfl_xor_sync(0xffffffffu, su2L, o);
    }
    if (lane == 0) { g_deg[n] = dg; g_Su[n] = suL; g_Su2[n] = su2L; }
}

// ---------------- aggregation passes: warp/node, 2 neighbors per iter, float4 ----------------
__global__ void k_pass1(const float* __restrict__ lm) {
    __shared__ int sI[8][MAXD];
    __shared__ float sU[8][MAXD];
    int w = threadIdx.x >> 5;
    int lane = threadIdx.x & 31;
    int n = (blockIdx.x * blockDim.x + threadIdx.x) >> 5;
    if (n >= NN) return;
    int dg = g_deg[n];
    int dgp = (dg + 1) & ~1;
    const size_t base = (size_t)n * MAXD;
    for (int i = lane; i < dgp; i += 32) {
        sI[w][i] = g_csr[base + i];
        sU[w][i] = g_uS[base + i];
    }
    __syncwarp();
    int half = lane >> 4, sub = lane & 15;
    const char* hb = (const char*)g_h + sub * 16;
    float4 m0 = f4zero(), suh = f4zero();
#pragma unroll 4
    for (int it = half; it < dgp; it += 2) {
        int off = sI[w][it];
        float us = sU[w][it];
        float4 v = *(const float4*)(hb + off);
        f4acc(m0, v);
        f4fma(suh, us, v);
    }
    f4xor16(m0); f4xor16(suh);
    if (lane < 16) {
        float lam = lm[0];
        float ud = u_of_deg(dg, lam);
        float4 hd = *(const float4*)(g_h + (size_t)n * D + sub * 4);
        float4 a1;
        if (dg == 1) a1 = hd;
        else {
            a1.x = (1.f - lam) * hd.x + ud * m0.x;
            a1.y = (1.f - lam) * hd.y + ud * m0.y;
            a1.z = (1.f - lam) * hd.z + ud * m0.z;
            a1.w = (1.f - lam) * hd.w + ud * m0.w;
        }
        *(float4*)(g_A1 + (size_t)n * D + sub * 4) = a1;
        *(float4*)(g_Suh + (size_t)n * D + sub * 4) = suh;
    }
}

__global__ void k_pass2(const float* __restrict__ lm) {
    __shared__ int sI[8][MAXD];
    __shared__ float sU[8][MAXD];
    int w = threadIdx.x >> 5;
    int lane = threadIdx.x & 31;
    int n = (blockIdx.x * blockDim.x + threadIdx.x) >> 5;
    if (n >= NN) return;
    int dg = g_deg[n];
    int dgp = (dg + 1) & ~1;
    const size_t base = (size_t)n * MAXD;
    for (int i = lane; i < dgp; i += 32) {
        sI[w][i] = g_csr[base + i];
        sU[w][i] = g_uS[base + i];
    }
    __syncwarp();
    int half = lane >> 4, sub = lane & 15;
    const char* ab = (const char*)g_A1 + sub * 16;
    float4 sa1 = f4zero(), sua1 = f4zero();
#pragma unroll 4
    for (int it = half; it < dgp; it += 2) {
        int off = sI[w][it];
        float us = sU[w][it];
        float4 v = *(const float4*)(ab + off);
        f4acc(sa1, v);
        f4fma(sua1, us, v);
    }
    f4xor16(sa1); f4xor16(sua1);
    if (lane < 16) {
        float lam = lm[0];
        float su = g_Su[n];
        float ud = u_of_deg(dg, lam);
        float4 hd = *(const float4*)(g_h + (size_t)n * D + sub * 4);
        float4 a2;
        if (dg == 1) a2 = hd;
        else {
            a2.x = (1.f - lam) * hd.x + ud * (sa1.x - su * hd.x);
            a2.y = (1.f - lam) * hd.y + ud * (sa1.y - su * hd.y);
            a2.z = (1.f - lam) * hd.z + ud * (sa1.z - su * hd.z);
            a2.w = (1.f - lam) * hd.w + ud * (sa1.w - su * hd.w);
        }
        *(float4*)(g_A2 + (size_t)n * D + sub * 4) = a2;
        *(float4*)(g_SuA1 + (size_t)n * D + sub * 4) = sua1;
    }
}

__global__ void k_pass3(const float* __restrict__ lm) {
    __shared__ int sI[8][MAXD];
    int w = threadIdx.x >> 5;
    int lane = threadIdx.x & 31;
    int n = (blockIdx.x * blockDim.x + threadIdx.x) >> 5;
    if (n >= NN) return;
    int dg = g_deg[n];
    int dgp = (dg + 1) & ~1;
    const size_t base = (size_t)n * MAXD;
    for (int i = lane; i < dgp; i += 32) sI[w][i] = g_csr[base + i];
    __syncwarp();
    int half = lane >> 4, sub = lane & 15;
    const char* ab = (const char*)g_A2 + sub * 16;
    float4 sa2 = f4zero();
#pragma unroll 4
    for (int it = half; it < dgp; it += 2) {
        int off = sI[w][it];
        float4 v = *(const float4*)(ab + off);
        f4acc(sa2, v);
    }
    f4xor16(sa2);
    if (lane < 16) {
        float lam = lm[0];
        float su = g_Su[n];
        float ud = u_of_deg(dg, lam);
        float4 hd = *(const float4*)(g_h + (size_t)n * D + sub * 4);
        float4 a1d = *(const float4*)(g_A1 + (size_t)n * D + sub * 4);
        float4 suhd = *(const float4*)(g_Suh + (size_t)n * D + sub * 4);
        float4 a3;
        if (dg == 1) a3 = hd;
        else {
            a3.x = (1.f - lam) * hd.x + ud * (sa2.x - su * a1d.x + ud * suhd.x);
            a3.y = (1.f - lam) * hd.y + ud * (sa2.y - su * a1d.y + ud * suhd.y);
            a3.z = (1.f - lam) * hd.z + ud * (sa2.z - su * a1d.z + ud * suhd.z);
            a3.w = (1.f - lam) * hd.w + ud * (sa2.w - su * a1d.w + ud * suhd.w);
        }
        *(float4*)(g_A3 + (size_t)n * D + sub * 4) = a3;
    }
}

__global__ void k_pass4(const float* __restrict__ lm, const float* __restrict__ x,
                        float* __restrict__ out) {
    __shared__ int sI[8][MAXD];
    int w = threadIdx.x >> 5;
    int lane = threadIdx.x & 31;
    int n = (blockIdx.x * blockDim.x + threadIdx.x) >> 5;
    if (n >= NN) return;
    int dg = g_deg[n];
    int dgp = (dg + 1) & ~1;
    const size_t base = (size_t)n * MAXD;
    for (int i = lane; i < dgp; i += 32) sI[w][i] = g_csr[base + i];
    __syncwarp();
    int half = lane >> 4, sub = lane & 15;
    const char* ab = (const char*)g_A3 + sub * 16;
    float4 sa3 = f4zero();
#pragma unroll 4
    for (int it = half; it < dgp; it += 2) {
        int off = sI[w][it];
        float4 v = *(const float4*)(ab + off);
        f4acc(sa3, v);
    }
    f4xor16(sa3);
    if (lane < 16) {
        float lam = lm[0];
        float su = g_Su[n];
        float su2 = g_Su2[n];
        float ud = u_of_deg(dg, lam);
        float4 hd = *(const float4*)(g_h + (size_t)n * D + sub * 4);
        float4 a2d = *(const float4*)(g_A2 + (size_t)n * D + sub * 4);
        float4 sua1d = *(const float4*)(g_SuA1 + (size_t)n * D + sub * 4);
        float4 xd = *(const float4*)(x + (size_t)n * D + sub * 4);
        float4 tmp;
        if (dg == 0) {
            tmp = hd;
        } else {
            float c = lam / ((float)dg + EPSF);
            float us2 = ud * su2;
            tmp.x = (1.f - lam) * hd.x + c * (sa3.x - su * a2d.x + ud * sua1d.x - us2 * hd.x);
            tmp.y = (1.f - lam) * hd.y + c * (sa3.y - su * a2d.y + ud * sua1d.y - us2 * hd.y);
            tmp.z = (1.f - lam) * hd.z + c * (sa3.z - su * a2d.z + ud * sua1d.z - us2 * hd.z);
            tmp.w = (1.f - lam) * hd.w + c * (sa3.w - su * a2d.w + ud * sua1d.w - us2 * hd.w);
        }
        float4 o;
        o.x = xd.x + fmaxf(tmp.x, 0.f);
        o.y = xd.y + fmaxf(tmp.y, 0.f);
        o.z = xd.z + fmaxf(tmp.z, 0.f);
        o.w = xd.w + fmaxf(tmp.w, 0.f);
        *(float4*)(out + (size_t)n * D + sub * 4) = o;
    }
}

extern "C" void kernel_launch(void* const* d_in, const int* in_sizes, int n_in,
                              void* d_out, int out_size) {
    const float* x = (const float*)d_in[0];
    const int* edge_index = (const int*)d_in[1];
    const float* W = (const float*)d_in[2];
    const float* b = (const float*)d_in[3];
    const float* lm = (const float*)d_in[4];
    float* out = (float*)d_out;

    const int* src = edge_index;        // row 0
    const int* dst = edge_index + EE;   // row 1

    k_gemm<<<(NN + 127) / 128, 128>>>(x, W, b);
    k_fill<<<(EE / 4 + 255) / 256, 256>>>(src, dst);
    int wblocks = (NN * 32 + 255) / 256;
    k_sortu<<<wblocks, 256>>>(lm);
    k_pass1<<<wblocks, 256>>>(lm);
    k_pass2<<<wblocks, 256>>>(lm);
    k_pass3<<<wblocks, 256>>>(lm);
    k_pass4<<<wblocks, 256>>>(lm, x, out);
}

// round 14
// speedup vs baseline: 1.5737x; 1.0033x over previous
#include <cuda_runtime.h>
#include <cstdint>

#define NN 100000
#define EE 1600000
#define D 64
#define MAXD 96
#define EPSF 1e-9f
#define IMAX 0x7fffffff

#define GRID_CTAS (148 * 6)
#define TOT_WARPS (GRID_CTAS * 8)

// ---- static device scratch (no allocation allowed) ----
__device__ float g_h[(NN + 1) * D];
__device__ float g_A1[(NN + 1) * D];
__device__ float g_A2[(NN + 1) * D];
__device__ float g_A3[(NN + 1) * D];
__device__ float g_Suh[NN * D];
__device__ float g_SuA1[NN * D];
__device__ int   g_deg[NN];
__device__ int   g_cursor[NN];
__device__ float g_Su[NN];
__device__ float g_Su2[NN];
__device__ int   g_csr[(size_t)NN * MAXD];   // byte offsets (s * 256) after sort phase
__device__ float g_uS[(size_t)NN * MAXD];
__device__ int      g_bar_count;
__device__ unsigned g_bar_gen;

__device__ __forceinline__ float4 f4zero() { return make_float4(0.f, 0.f, 0.f, 0.f); }
__device__ __forceinline__ void f4acc(float4& a, const float4 v) {
    a.x += v.x; a.y += v.y; a.z += v.z; a.w += v.w;
}
__device__ __forceinline__ void f4fma(float4& a, float c, const float4 v) {
    a.x = fmaf(c, v.x, a.x); a.y = fmaf(c, v.y, a.y);
    a.z = fmaf(c, v.z, a.z); a.w = fmaf(c, v.w, a.w);
}
__device__ __forceinline__ void f4xor16(float4& a) {
    a.x += __shfl_xor_sync(0xffffffffu, a.x, 16);
    a.y += __shfl_xor_sync(0xffffffffu, a.y, 16);
    a.z += __shfl_xor_sync(0xffffffffu, a.z, 16);
    a.w += __shfl_xor_sync(0xffffffffu, a.w, 16);
}
__device__ __forceinline__ float u_of_deg(int dg, float lam) {
    return (dg <= 1) ? 0.f : lam / ((float)dg - 1.0f + EPSF);
}

// counter+generation grid barrier; all GRID_CTAS co-resident by __launch_bounds__
__device__ __forceinline__ void grid_sync() {
    __syncthreads();
    if (threadIdx.x == 0) {
        unsigned gen = *((volatile unsigned*)&g_bar_gen);
        __threadfence();
        if (atomicAdd(&g_bar_count, 1) == GRID_CTAS - 1) {
            g_bar_count = 0;
            __threadfence();
            atomicExch(&g_bar_gen, gen + 1);   // release
        } else {
            while (*((volatile unsigned*)&g_bar_gen) == gen) __nanosleep(64);
        }
        __threadfence();
    }
    __syncthreads();
}

// ---------------- h = x @ W + b  (also zeroes cursor + sentinel rows) ----------------
__global__ void k_gemm(const float* __restrict__ x, const float* __restrict__ W,
                       const float* __restrict__ b) {
    __shared__ float Ws[D * D];
    __shared__ float bs[D];
    for (int i = threadIdx.x; i < D * D; i += blockDim.x) Ws[i] = W[i];
    if (threadIdx.x < D) bs[threadIdx.x] = b[threadIdx.x];
    __syncthreads();
    int row = blockIdx.x * blockDim.x + threadIdx.x;
    if (blockIdx.x == 0 && threadIdx.x < D) {
        g_h[NN * D + threadIdx.x] = 0.f;
        g_A1[NN * D + threadIdx.x] = 0.f;
        g_A2[NN * D + threadIdx.x] = 0.f;
        g_A3[NN * D + threadIdx.x] = 0.f;
    }
    if (row >= NN) return;
    g_cursor[row] = 0;
    float acc[D];
#pragma unroll
    for (int j = 0; j < D; j++) acc[j] = bs[j];
    const float4* xr = (const float4*)(x + (size_t)row * D);
#pragma unroll 2
    for (int k4 = 0; k4 < 16; k4++) {
        float4 xv = xr[k4];
#pragma unroll
        for (int kk = 0; kk < 4; kk++) {
            float xk = (kk == 0) ? xv.x : (kk == 1) ? xv.y : (kk == 2) ? xv.z : xv.w;
            const float4* wr = (const float4*)&Ws[(k4 * 4 + kk) * D];
#pragma unroll
            for (int j4 = 0; j4 < 16; j4++) {
                float4 w = wr[j4];
                acc[j4 * 4 + 0] += xk * w.x;
                acc[j4 * 4 + 1] += xk * w.y;
                acc[j4 * 4 + 2] += xk * w.z;
                acc[j4 * 4 + 3] += xk * w.w;
            }
        }
    }
    float4* hr = (float4*)(g_h + (size_t)row * D);
#pragma unroll
    for (int j4 = 0; j4 < 16; j4++)
        hr[j4] = make_float4(acc[j4 * 4], acc[j4 * 4 + 1], acc[j4 * 4 + 2], acc[j4 * 4 + 3]);
}

// ---------------- CSR fill (scalar, proven fastest) ----------------
__global__ void k_fill(const int* __restrict__ src, const int* __restrict__ dst) {
    int e = blockIdx.x * blockDim.x + threadIdx.x;
    if (e >= EE) return;
    int d = dst[e];
    int pos = atomicAdd(&g_cursor[d], 1);
    if (pos < MAXD) g_csr[(size_t)d * MAXD + pos] = src[e];
}

// ================= fused persistent kernel: sort + 4 passes =================

__device__ __forceinline__ void phase_sortu(int n, int lane, float lam) {
    int dg = min(g_cursor[n], MAXD);
    const size_t base = (size_t)n * MAXD;
    float u0 = 0.f, u1 = 0.f;

    if (dg <= 32) {
        int v0 = (lane < dg) ? g_csr[base + lane] : IMAX;
#pragma unroll
        for (int k = 2; k <= 32; k <<= 1) {
#pragma unroll
            for (int j = k >> 1; j > 0; j >>= 1) {
                int p = __shfl_xor_sync(0xffffffffu, v0, j);
                bool up = ((lane & j) == 0);
                bool dir = ((lane & k) == 0) || (k == 32);
                v0 = (up == dir) ? min(v0, p) : max(v0, p);
            }
        }
        if (lane < dg) {
            int c0 = min(__ldg(&g_cursor[v0]), MAXD);
            u0 = u_of_deg(c0, lam);
            g_csr[base + lane] = v0 << 8;
            g_uS[base + lane] = u0;
        }
    } else {
        int v0 = (lane < dg) ? g_csr[base + lane] : IMAX;
        int v1 = (lane + 32 < dg) ? g_csr[base + lane + 32] : IMAX;
#pragma unroll
        for (int k = 2; k <= 64; k <<= 1) {
#pragma unroll
            for (int j = k >> 1; j > 0; j >>= 1) {
                if (j == 32) {
                    bool dir = ((lane & k) == 0) || (k == 64);
                    int lo = min(v0, v1), hi = max(v0, v1);
                    v0 = dir ? lo : hi;
                    v1 = dir ? hi : lo;
                } else {
                    int p0 = __shfl_xor_sync(0xffffffffu, v0, j);
                    bool up0 = ((lane & j) == 0);
                    bool dir0 = ((lane & k) == 0) || (k == 64);
                    v0 = (up0 == dir0) ? min(v0, p0) : max(v0, p0);
                    int p1 = __shfl_xor_sync(0xffffffffu, v1, j);
                    int idx1 = lane + 32;
                    bool up1 = ((idx1 & j) == 0);
                    bool dir1 = ((idx1 & k) == 0) || (k == 64);
                    v1 = (up1 == dir1) ? min(v1, p1) : max(v1, p1);
                }
            }
        }
        if (lane < dg) {
            int c0 = min(__ldg(&g_cursor[v0]), MAXD);
            u0 = u_of_deg(c0, lam);
            g_csr[base + lane] = v0 << 8;
            g_uS[base + lane] = u0;
        }
        if (lane + 32 < dg) {
            int c1 = min(__ldg(&g_cursor[v1]), MAXD);
            u1 = u_of_deg(c1, lam);
            g_csr[base + lane + 32] = v1 << 8;
            g_uS[base + lane + 32] = u1;
        }
    }
    if (lane < 2 && dg + lane < MAXD) {
        g_csr[base + dg + lane] = NN << 8;
        g_uS[base + dg + lane] = 0.f;
    }
    float suL = u0 + u1;
    float su2L = u0 * u0 + u1 * u1;
    for (int o = 16; o > 0; o >>= 1) {
        suL += __shfl_xor_sync(0xffffffffu, suL, o);
        su2L += __shfl_xor_sync(0xffffffffu, su2L, o);
    }
    if (lane == 0) { g_deg[n] = dg; g_Su[n] = suL; g_Su2[n] = su2L; }
}

__device__ __forceinline__ void phase_p1(int n, int w, int lane, float lam,
                                         int (*sI)[MAXD], float (*sU)[MAXD]) {
    int dg = g_deg[n];
    int dgp = (dg + 1) & ~1;
    const size_t base = (size_t)n * MAXD;
    for (int i = lane; i < dgp; i += 32) {
        sI[w][i] = g_csr[base + i];
        sU[w][i] = g_uS[base + i];
    }
    __syncwarp();
    int half = lane >> 4, sub = lane & 15;
    const char* hb = (const char*)g_h + sub * 16;
    float4 m0 = f4zero(), suh = f4zero();
#pragma unroll 4
    for (int it = half; it < dgp; it += 2) {
        int off = sI[w][it];
        float us = sU[w][it];
        float4 v = *(const float4*)(hb + off);
        f4acc(m0, v);
        f4fma(suh, us, v);
    }
    f4xor16(m0); f4xor16(suh);
    if (lane < 16) {
        float ud = u_of_deg(dg, lam);
        float4 hd = *(const float4*)(g_h + (size_t)n * D + sub * 4);
        float4 a1;
        if (dg == 1) a1 = hd;
        else {
            a1.x = (1.f - lam) * hd.x + ud * m0.x;
            a1.y = (1.f - lam) * hd.y + ud * m0.y;
            a1.z = (1.f - lam) * hd.z + ud * m0.z;
            a1.w = (1.f - lam) * hd.w + ud * m0.w;
        }
        *(float4*)(g_A1 + (size_t)n * D + sub * 4) = a1;
        *(float4*)(g_Suh + (size_t)n * D + sub * 4) = suh;
    }
    __syncwarp();
}

__device__ __forceinline__ void phase_p2(int n, int w, int lane, float lam,
                                         int (*sI)[MAXD], float (*sU)[MAXD]) {
    int dg = g_deg[n];
    int dgp = (dg + 1) & ~1;
    const size_t base = (size_t)n * MAXD;
    for (int i = lane; i < dgp; i += 32) {
        sI[w][i] = g_csr[base + i];
        sU[w][i] = g_uS[base + i];
    }
    __syncwarp();
    int half = lane >> 4, sub = lane & 15;
    const char* ab = (const char*)g_A1 + sub * 16;
    float4 sa1 = f4zero(), sua1 = f4zero();
#pragma unroll 4
    for (int it = half; it < dgp; it += 2) {
        int off = sI[w][it];
        float us = sU[w][it];
        float4 v = *(const float4*)(ab + off);
        f4acc(sa1, v);
        f4fma(sua1, us, v);
    }
    f4xor16(sa1); f4xor16(sua1);
    if (lane < 16) {
        float su = g_Su[n];
        float ud = u_of_deg(dg, lam);
        float4 hd = *(const float4*)(g_h + (size_t)n * D + sub * 4);
        float4 a2;
        if (dg == 1) a2 = hd;
        else {
            a2.x = (1.f - lam) * hd.x + ud * (sa1.x - su * hd.x);
            a2.y = (1.f - lam) * hd.y + ud * (sa1.y - su * hd.y);
            a2.z = (1.f - lam) * hd.z + ud * (sa1.z - su * hd.z);
            a2.w = (1.f - lam) * hd.w + ud * (sa1.w - su * hd.w);
        }
        *(float4*)(g_A2 + (size_t)n * D + sub * 4) = a2;
        *(float4*)(g_SuA1 + (size_t)n * D + sub * 4) = sua1;
    }
    __syncwarp();
}

__device__ __forceinline__ void phase_p3(int n, int w, int lane, float lam,
                                         int (*sI)[MAXD]) {
    int dg = g_deg[n];
    int dgp = (dg + 1) & ~1;
    const size_t base = (size_t)n * MAXD;
    for (int i = lane; i < dgp; i += 32) sI[w][i] = g_csr[base + i];
    __syncwarp();
    int half = lane >> 4, sub = lane & 15;
    const char* ab = (const char*)g_A2 + sub * 16;
    float4 sa2 = f4zero();
#pragma unroll 4
    for (int it = half; it < dgp; it += 2) {
        int off = sI[w][it];
        float4 v = *(const float4*)(ab + off);
        f4acc(sa2, v);
    }
    f4xor16(sa2);
    if (lane < 16) {
        float su = g_Su[n];
        float ud = u_of_deg(dg, lam);
        float4 hd = *(const float4*)(g_h + (size_t)n * D + sub * 4);
        float4 a1d = *(const float4*)(g_A1 + (size_t)n * D + sub * 4);
        float4 suhd = *(const float4*)(g_Suh + (size_t)n * D + sub * 4);
        float4 a3;
        if (dg == 1) a3 = hd;
        else {
            a3.x = (1.f - lam) * hd.x + ud * (sa2.x - su * a1d.x + ud * suhd.x);
            a3.y = (1.f - lam) * hd.y + ud * (sa2.y - su * a1d.y + ud * suhd.y);
            a3.z = (1.f - lam) * hd.z + ud * (sa2.z - su * a1d.z + ud * suhd.z);
            a3.w = (1.f - lam) * hd.w + ud * (sa2.w - su * a1d.w + ud * suhd.w);
        }
        *(float4*)(g_A3 + (size_t)n * D + sub * 4) = a3;
    }
    __syncwarp();
}

__device__ __forceinline__ void phase_p4(int n, int w, int lane, float lam,
                                         const float* __restrict__ x,
                                         float* __restrict__ out,
                                         int (*sI)[MAXD]) {
    int dg = g_deg[n];
    int dgp = (dg + 1) & ~1;
    const size_t base = (size_t)n * MAXD;
    for (int i = lane; i < dgp; i += 32) sI[w][i] = g_csr[base + i];
    __syncwarp();
    int half = lane >> 4, sub = lane & 15;
    const char* ab = (const char*)g_A3 + sub * 16;
    float4 sa3 = f4zero();
#pragma unroll 4
    for (int it = half; it < dgp; it += 2) {
        int off = sI[w][it];
        float4 v = *(const float4*)(ab + off);
        f4acc(sa3, v);
    }
    f4xor16(sa3);
    if (lane < 16) {
        float su = g_Su[n];
        float su2 = g_Su2[n];
        float ud = u_of_deg(dg, lam);
        float4 hd = *(const float4*)(g_h + (size_t)n * D + sub * 4);
        float4 a2d = *(const float4*)(g_A2 + (size_t)n * D + sub * 4);
        float4 sua1d = *(const float4*)(g_SuA1 + (size_t)n * D + sub * 4);
        float4 xd = *(const float4*)(x + (size_t)n * D + sub * 4);
        float4 tmp;
        if (dg == 0) {
            tmp = hd;
        } else {
            float c = lam / ((float)dg + EPSF);
            float us2 = ud * su2;
            tmp.x = (1.f - lam) * hd.x + c * (sa3.x - su * a2d.x + ud * sua1d.x - us2 * hd.x);
            tmp.y = (1.f - lam) * hd.y + c * (sa3.y - su * a2d.y + ud * sua1d.y - us2 * hd.y);
            tmp.z = (1.f - lam) * hd.z + c * (sa3.z - su * a2d.z + ud * sua1d.z - us2 * hd.z);
            tmp.w = (1.f - lam) * hd.w + c * (sa3.w - su * a2d.w + ud * sua1d.w - us2 * hd.w);
        }
        float4 o;
        o.x = xd.x + fmaxf(tmp.x, 0.f);
        o.y = xd.y + fmaxf(tmp.y, 0.f);
        o.z = xd.z + fmaxf(tmp.z, 0.f);
        o.w = xd.w + fmaxf(tmp.w, 0.f);
        *(float4*)(out + (size_t)n * D + sub * 4) = o;
    }
    __syncwarp();
}

__global__ void __launch_bounds__(256, 6)
k_fused(const float* __restrict__ lm, const float* __restrict__ x,
        float* __restrict__ out) {
    __shared__ int sI[8][MAXD];
    __shared__ float sU[8][MAXD];
    int w = threadIdx.x >> 5;
    int lane = threadIdx.x & 31;
    int wid0 = (blockIdx.x * 256 + threadIdx.x) >> 5;
    float lam = lm[0];

    for (int n = wid0; n < NN; n += TOT_WARPS) phase_sortu(n, lane, lam);
    grid_sync();
    for (int n = wid0; n < NN; n += TOT_WARPS) phase_p1(n, w, lane, lam, sI, sU);
    grid_sync();
    for (int n = wid0; n < NN; n += TOT_WARPS) phase_p2(n, w, lane, lam, sI, sU);
    grid_sync();
    for (int n = wid0; n < NN; n += TOT_WARPS) phase_p3(n, w, lane, lam, sI);
    grid_sync();
    for (int n = wid0; n < NN; n += TOT_WARPS) phase_p4(n, w, lane, lam, x, out, sI);
}

extern "C" void kernel_launch(void* const* d_in, const int* in_sizes, int n_in,
                              void* d_out, int out_size) {
    const float* x = (const float*)d_in[0];
    const int* edge_index = (const int*)d_in[1];
    const float* W = (const float*)d_in[2];
    const float* b = (const float*)d_in[3];
    const float* lm = (const float*)d_in[4];
    float* out = (float*)d_out;

    const int* src = edge_index;        // row 0
    const int* dst = edge_index + EE;   // row 1

    k_gemm<<<(NN + 127) / 128, 128>>>(x, W, b);
    k_fill<<<(EE + 255) / 256, 256>>>(src, dst);
    k_fused<<<GRID_CTAS, 256>>>(lm, x, out);
}

// round 15
// speedup vs baseline: 1.6439x; 1.0446x over previous
#include <cuda_runtime.h>
#include <cstdint>

#define NN 100000
#define EE 1600000
#define D 64
#define MAXD 96
#define EPSF 1e-9f
#define IMAX 0x7fffffff

#define GRID_CTAS (148 * 6)
#define TOT_WARPS (GRID_CTAS * 8)

// ---- static device scratch (no allocation allowed) ----
__device__ float g_h[(NN + 1) * D];
__device__ float g_A1[(NN + 1) * D];
__device__ float g_A2[(NN + 1) * D];
__device__ float g_A3[(NN + 1) * D];
__device__ float g_Suh[NN * D];
__device__ float g_SuA1[NN * D];
__device__ int   g_deg[NN];
__device__ int   g_cursor[NN];
__device__ float g_Su[NN];
__device__ float g_Su2[NN];
__device__ int   g_csr[(size_t)NN * MAXD];   // byte offsets (s * 256) after sort phase
__device__ float g_uS[(size_t)NN * MAXD];
__device__ int      g_bar_count;
__device__ unsigned g_bar_gen;

__device__ __forceinline__ float4 f4zero() { return make_float4(0.f, 0.f, 0.f, 0.f); }
__device__ __forceinline__ void f4acc(float4& a, const float4 v) {
    a.x += v.x; a.y += v.y; a.z += v.z; a.w += v.w;
}
__device__ __forceinline__ void f4fma(float4& a, float c, const float4 v) {
    a.x = fmaf(c, v.x, a.x); a.y = fmaf(c, v.y, a.y);
    a.z = fmaf(c, v.z, a.z); a.w = fmaf(c, v.w, a.w);
}
__device__ __forceinline__ void f4xor16(float4& a) {
    a.x += __shfl_xor_sync(0xffffffffu, a.x, 16);
    a.y += __shfl_xor_sync(0xffffffffu, a.y, 16);
    a.z += __shfl_xor_sync(0xffffffffu, a.z, 16);
    a.w += __shfl_xor_sync(0xffffffffu, a.w, 16);
}
__device__ __forceinline__ float u_of_deg(int dg, float lam) {
    return (dg <= 1) ? 0.f : lam / ((float)dg - 1.0f + EPSF);
}

// counter+generation grid barrier; all GRID_CTAS co-resident by __launch_bounds__
__device__ __forceinline__ void grid_sync() {
    __syncthreads();
    if (threadIdx.x == 0) {
        unsigned gen = *((volatile unsigned*)&g_bar_gen);
        __threadfence();
        if (atomicAdd(&g_bar_count, 1) == GRID_CTAS - 1) {
            g_bar_count = 0;
            __threadfence();
            atomicExch(&g_bar_gen, gen + 1);   // release
        } else {
            while (*((volatile unsigned*)&g_bar_gen) == gen) __nanosleep(64);
        }
        __threadfence();
    }
    __syncthreads();
}

// ---------------- h = x @ W + b : register-tiled GEMM (64x64 tile, 4x4/thread) ----------------
__global__ void __launch_bounds__(256) k_gemm(const float* __restrict__ x,
                                              const float* __restrict__ W,
                                              const float* __restrict__ b) {
    __shared__ float xs[D][68];   // transposed x tile, padded for 16B-aligned float4
    __shared__ float Ws[D * D];
    __shared__ float bs[D];
    int tid = threadIdx.x;
    int base = blockIdx.x * 64;

    int zi = blockIdx.x * 256 + tid;
    if (zi < NN) g_cursor[zi] = 0;
    if (blockIdx.x == 0 && tid < D) {
        g_h[NN * D + tid] = 0.f;
        g_A1[NN * D + tid] = 0.f;
        g_A2[NN * D + tid] = 0.f;
        g_A3[NN * D + tid] = 0.f;
    }

    // stage W (row-major) + bias
    for (int i = tid; i < D * D / 4; i += 256)
        ((float4*)Ws)[i] = ((const float4*)W)[i];
    if (tid < D) bs[tid] = b[tid];

    // stage x tile transposed: xs[k][row]
    for (int idx = tid; idx < 64 * 16; idx += 256) {
        int row = idx >> 4, c4 = idx & 15;
        int grow = base + row;
        float4 v = (grow < NN) ? *(const float4*)(x + (size_t)grow * D + c4 * 4) : f4zero();
        xs[c4 * 4 + 0][row] = v.x;
        xs[c4 * 4 + 1][row] = v.y;
        xs[c4 * 4 + 2][row] = v.z;
        xs[c4 * 4 + 3][row] = v.w;
    }
    __syncthreads();

    int tr = tid >> 4, tc = tid & 15;   // rows tr*4.., cols tc*4..
    float acc[4][4];
#pragma unroll
    for (int i = 0; i < 4; i++) {
        acc[i][0] = bs[tc * 4 + 0];
        acc[i][1] = bs[tc * 4 + 1];
        acc[i][2] = bs[tc * 4 + 2];
        acc[i][3] = bs[tc * 4 + 3];
    }
#pragma unroll 8
    for (int k = 0; k < D; k++) {
        float4 a = *(const float4*)&xs[k][tr * 4];
        float4 wv = *(const float4*)&Ws[k * D + tc * 4];
        acc[0][0] = fmaf(a.x, wv.x, acc[0][0]); acc[0][1] = fmaf(a.x, wv.y, acc[0][1]);
        acc[0][2] = fmaf(a.x, wv.z, acc[0][2]); acc[0][3] = fmaf(a.x, wv.w, acc[0][3]);
        acc[1][0] = fmaf(a.y, wv.x, acc[1][0]); acc[1][1] = fmaf(a.y, wv.y, acc[1][1]);
        acc[1][2] = fmaf(a.y, wv.z, acc[1][2]); acc[1][3] = fmaf(a.y, wv.w, acc[1][3]);
        acc[2][0] = fmaf(a.z, wv.x, acc[2][0]); acc[2][1] = fmaf(a.z, wv.y, acc[2][1]);
        acc[2][2] = fmaf(a.z, wv.z, acc[2][2]); acc[2][3] = fmaf(a.z, wv.w, acc[2][3]);
        acc[3][0] = fmaf(a.w, wv.x, acc[3][0]); acc[3][1] = fmaf(a.w, wv.y, acc[3][1]);
        acc[3][2] = fmaf(a.w, wv.z, acc[3][2]); acc[3][3] = fmaf(a.w, wv.w, acc[3][3]);
    }
#pragma unroll
    for (int i = 0; i < 4; i++) {
        int row = base + tr * 4 + i;
        if (row < NN)
            *(float4*)(g_h + (size_t)row * D + tc * 4) =
                make_float4(acc[i][0], acc[i][1], acc[i][2], acc[i][3]);
    }
}

// ---------------- CSR fill (scalar, proven fastest) ----------------
__global__ void k_fill(const int* __restrict__ src, const int* __restrict__ dst) {
    int e = blockIdx.x * blockDim.x + threadIdx.x;
    if (e >= EE) return;
    int d = dst[e];
    int pos = atomicAdd(&g_cursor[d], 1);
    if (pos < MAXD) g_csr[(size_t)d * MAXD + pos] = src[e];
}

// ================= fused persistent kernel: sort + 4 passes =================

__device__ __forceinline__ void phase_sortu(int n, int lane, float lam) {
    int dg = min(g_cursor[n], MAXD);
    const size_t base = (size_t)n * MAXD;
    float u0 = 0.f, u1 = 0.f;

    if (dg <= 32) {
        int v0 = (lane < dg) ? g_csr[base + lane] : IMAX;
#pragma unroll
        for (int k = 2; k <= 32; k <<= 1) {
#pragma unroll
            for (int j = k >> 1; j > 0; j >>= 1) {
                int p = __shfl_xor_sync(0xffffffffu, v0, j);
                bool up = ((lane & j) == 0);
                bool dir = ((lane & k) == 0) || (k == 32);
                v0 = (up == dir) ? min(v0, p) : max(v0, p);
            }
        }
        if (lane < dg) {
            int c0 = min(__ldg(&g_cursor[v0]), MAXD);
            u0 = u_of_deg(c0, lam);
            g_csr[base + lane] = v0 << 8;
            g_uS[base + lane] = u0;
        }
    } else {
        int v0 = (lane < dg) ? g_csr[base + lane] : IMAX;
        int v1 = (lane + 32 < dg) ? g_csr[base + lane + 32] : IMAX;
#pragma unroll
        for (int k = 2; k <= 64; k <<= 1) {
#pragma unroll
            for (int j = k >> 1; j > 0; j >>= 1) {
                if (j == 32) {
                    bool dir = ((lane & k) == 0) || (k == 64);
                    int lo = min(v0, v1), hi = max(v0, v1);
                    v0 = dir ? lo : hi;
                    v1 = dir ? hi : lo;
                } else {
                    int p0 = __shfl_xor_sync(0xffffffffu, v0, j);
                    bool up0 = ((lane & j) == 0);
                    bool dir0 = ((lane & k) == 0) || (k == 64);
                    v0 = (up0 == dir0) ? min(v0, p0) : max(v0, p0);
                    int p1 = __shfl_xor_sync(0xffffffffu, v1, j);
                    int idx1 = lane + 32;
                    bool up1 = ((idx1 & j) == 0);
                    bool dir1 = ((idx1 & k) == 0) || (k == 64);
                    v1 = (up1 == dir1) ? min(v1, p1) : max(v1, p1);
                }
            }
        }
        if (lane < dg) {
            int c0 = min(__ldg(&g_cursor[v0]), MAXD);
            u0 = u_of_deg(c0, lam);
            g_csr[base + lane] = v0 << 8;
            g_uS[base + lane] = u0;
        }
        if (lane + 32 < dg) {
            int c1 = min(__ldg(&g_cursor[v1]), MAXD);
            u1 = u_of_deg(c1, lam);
            g_csr[base + lane + 32] = v1 << 8;
            g_uS[base + lane + 32] = u1;
        }
    }
    if (lane < 2 && dg + lane < MAXD) {
        g_csr[base + dg + lane] = NN << 8;
        g_uS[base + dg + lane] = 0.f;
    }
    float suL = u0 + u1;
    float su2L = u0 * u0 + u1 * u1;
    for (int o = 16; o > 0; o >>= 1) {
        suL += __shfl_xor_sync(0xffffffffu, suL, o);
        su2L += __shfl_xor_sync(0xffffffffu, su2L, o);
    }
    if (lane == 0) { g_deg[n] = dg; g_Su[n] = suL; g_Su2[n] = su2L; }
}

__device__ __forceinline__ void phase_p1(int n, int w, int lane, float lam,
                                         int (*sI)[MAXD], float (*sU)[MAXD]) {
    int dg = g_deg[n];
    int dgp = (dg + 1) & ~1;
    const size_t base = (size_t)n * MAXD;
    for (int i = lane; i < dgp; i += 32) {
        sI[w][i] = g_csr[base + i];
        sU[w][i] = g_uS[base + i];
    }
    __syncwarp();
    int half = lane >> 4, sub = lane & 15;
    const char* hb = (const char*)g_h + sub * 16;
    float4 m0 = f4zero(), suh = f4zero();
#pragma unroll 4
    for (int it = half; it < dgp; it += 2) {
        int off = sI[w][it];
        float us = sU[w][it];
        float4 v = *(const float4*)(hb + off);
        f4acc(m0, v);
        f4fma(suh, us, v);
    }
    f4xor16(m0); f4xor16(suh);
    if (lane < 16) {
        float ud = u_of_deg(dg, lam);
        float4 hd = *(const float4*)(g_h + (size_t)n * D + sub * 4);
        float4 a1;
        if (dg == 1) a1 = hd;
        else {
            a1.x = (1.f - lam) * hd.x + ud * m0.x;
            a1.y = (1.f - lam) * hd.y + ud * m0.y;
            a1.z = (1.f - lam) * hd.z + ud * m0.z;
            a1.w = (1.f - lam) * hd.w + ud * m0.w;
        }
        *(float4*)(g_A1 + (size_t)n * D + sub * 4) = a1;
        *(float4*)(g_Suh + (size_t)n * D + sub * 4) = suh;
    }
    __syncwarp();
}

__device__ __forceinline__ void phase_p2(int n, int w, int lane, float lam,
                                         int (*sI)[MAXD], float (*sU)[MAXD]) {
    int dg = g_deg[n];
    int dgp = (dg + 1) & ~1;
    const size_t base = (size_t)n * MAXD;
    for (int i = lane; i < dgp; i += 32) {
        sI[w][i] = g_csr[base + i];
        sU[w][i] = g_uS[base + i];
    }
    __syncwarp();
    int half = lane >> 4, sub = lane & 15;
    const char* ab = (const char*)g_A1 + sub * 16;
    float4 sa1 = f4zero(), sua1 = f4zero();
#pragma unroll 4
    for (int it = half; it < dgp; it += 2) {
        int off = sI[w][it];
        float us = sU[w][it];
        float4 v = *(const float4*)(ab + off);
        f4acc(sa1, v);
        f4fma(sua1, us, v);
    }
    f4xor16(sa1); f4xor16(sua1);
    if (lane < 16) {
        float su = g_Su[n];
        float ud = u_of_deg(dg, lam);
        float4 hd = *(const float4*)(g_h + (size_t)n * D + sub * 4);
        float4 a2;
        if (dg == 1) a2 = hd;
        else {
            a2.x = (1.f - lam) * hd.x + ud * (sa1.x - su * hd.x);
            a2.y = (1.f - lam) * hd.y + ud * (sa1.y - su * hd.y);
            a2.z = (1.f - lam) * hd.z + ud * (sa1.z - su * hd.z);
            a2.w = (1.f - lam) * hd.w + ud * (sa1.w - su * hd.w);
        }
        *(float4*)(g_A2 + (size_t)n * D + sub * 4) = a2;
        *(float4*)(g_SuA1 + (size_t)n * D + sub * 4) = sua1;
    }
    __syncwarp();
}

__device__ __forceinline__ void phase_p3(int n, int w, int lane, float lam,
                                         int (*sI)[MAXD]) {
    int dg = g_deg[n];
    int dgp = (dg + 1) & ~1;
    const size_t base = (size_t)n * MAXD;
    for (int i = lane; i < dgp; i += 32) sI[w][i] = g_csr[base + i];
    __syncwarp();
    int half = lane >> 4, sub = lane & 15;
    const char* ab = (const char*)g_A2 + sub * 16;
    float4 sa2 = f4zero();
#pragma unroll 4
    for (int it = half; it < dgp; it += 2) {
        int off = sI[w][it];
        float4 v = *(const float4*)(ab + off);
        f4acc(sa2, v);
    }
    f4xor16(sa2);
    if (lane < 16) {
        float su = g_Su[n];
        float ud = u_of_deg(dg, lam);
        float4 hd = *(const float4*)(g_h + (size_t)n * D + sub * 4);
        float4 a1d = *(const float4*)(g_A1 + (size_t)n * D + sub * 4);
        float4 suhd = *(const float4*)(g_Suh + (size_t)n * D + sub * 4);
        float4 a3;
        if (dg == 1) a3 = hd;
        else {
            a3.x = (1.f - lam) * hd.x + ud * (sa2.x - su * a1d.x + ud * suhd.x);
            a3.y = (1.f - lam) * hd.y + ud * (sa2.y - su * a1d.y + ud * suhd.y);
            a3.z = (1.f - lam) * hd.z + ud * (sa2.z - su * a1d.z + ud * suhd.z);
            a3.w = (1.f - lam) * hd.w + ud * (sa2.w - su * a1d.w + ud * suhd.w);
        }
        *(float4*)(g_A3 + (size_t)n * D + sub * 4) = a3;
    }
    __syncwarp();
}

__device__ __forceinline__ void phase_p4(int n, int w, int lane, float lam,
                                         const float* __restrict__ x,
                                         float* __restrict__ out,
                                         int (*sI)[MAXD]) {
    int dg = g_deg[n];
    int dgp = (dg + 1) & ~1;
    const size_t base = (size_t)n * MAXD;
    for (int i = lane; i < dgp; i += 32) sI[w][i] = g_csr[base + i];
    __syncwarp();
    int half = lane >> 4, sub = lane & 15;
    const char* ab = (const char*)g_A3 + sub * 16;
    float4 sa3 = f4zero();
#pragma unroll 4
    for (int it = half; it < dgp; it += 2) {
        int off = sI[w][it];
        float4 v = *(const float4*)(ab + off);
        f4acc(sa3, v);
    }
    f4xor16(sa3);
    if (lane < 16) {
        float su = g_Su[n];
        float su2 = g_Su2[n];
        float ud = u_of_deg(dg, lam);
        float4 hd = *(const float4*)(g_h + (size_t)n * D + sub * 4);
        float4 a2d = *(const float4*)(g_A2 + (size_t)n * D + sub * 4);
        float4 sua1d = *(const float4*)(g_SuA1 + (size_t)n * D + sub * 4);
        float4 xd = *(const float4*)(x + (size_t)n * D + sub * 4);
        float4 tmp;
        if (dg == 0) {
            tmp = hd;
        } else {
            float c = lam / ((float)dg + EPSF);
            float us2 = ud * su2;
            tmp.x = (1.f - lam) * hd.x + c * (sa3.x - su * a2d.x + ud * sua1d.x - us2 * hd.x);
            tmp.y = (1.f - lam) * hd.y + c * (sa3.y - su * a2d.y + ud * sua1d.y - us2 * hd.y);
            tmp.z = (1.f - lam) * hd.z + c * (sa3.z - su * a2d.z + ud * sua1d.z - us2 * hd.z);
            tmp.w = (1.f - lam) * hd.w + c * (sa3.w - su * a2d.w + ud * sua1d.w - us2 * hd.w);
        }
        float4 o;
        o.x = xd.x + fmaxf(tmp.x, 0.f);
        o.y = xd.y + fmaxf(tmp.y, 0.f);
        o.z = xd.z + fmaxf(tmp.z, 0.f);
        o.w = xd.w + fmaxf(tmp.w, 0.f);
        *(float4*)(out + (size_t)n * D + sub * 4) = o;
    }
    __syncwarp();
}

__global__ void __launch_bounds__(256, 6)
k_fused(const float* __restrict__ lm, const float* __restrict__ x,
        float* __restrict__ out) {
    __shared__ int sI[8][MAXD];
    __shared__ float sU[8][MAXD];
    int w = threadIdx.x >> 5;
    int lane = threadIdx.x & 31;
    int wid0 = (blockIdx.x * 256 + threadIdx.x) >> 5;
    float lam = lm[0];

    for (int n = wid0; n < NN; n += TOT_WARPS) phase_sortu(n, lane, lam);
    grid_sync();
    for (int n = wid0; n < NN; n += TOT_WARPS) phase_p1(n, w, lane, lam, sI, sU);
    grid_sync();
    for (int n = wid0; n < NN; n += TOT_WARPS) phase_p2(n, w, lane, lam, sI, sU);
    grid_sync();
    for (int n = wid0; n < NN; n += TOT_WARPS) phase_p3(n, w, lane, lam, sI);
    grid_sync();
    for (int n = wid0; n < NN; n += TOT_WARPS) phase_p4(n, w, lane, lam, x, out, sI);
}

extern "C" void kernel_launch(void* const* d_in, const int* in_sizes, int n_in,
                              void* d_out, int out_size) {
    const float* x = (const float*)d_in[0];
    const int* edge_index = (const int*)d_in[1];
    const float* W = (const float*)d_in[2];
    const float* b = (const float*)d_in[3];
    const float* lm = (const float*)d_in[4];
    float* out = (float*)d_out;

    const int* src = edge_index;        // row 0
    const int* dst = edge_index + EE;   // row 1

    k_gemm<<<(NN + 63) / 64, 256>>>(x, W, b);
    k_fill<<<(EE + 255) / 256, 256>>>(src, dst);
    k_fused<<<GRID_CTAS, 256>>>(lm, x, out);
}

// round 17
// speedup vs baseline: 1.6535x; 1.0058x over previous
#include <cuda_runtime.h>
#include <cstdint>

#define NN 100000
#define EE 1600000
#define D 64
#define MAXD 96
#define EPSF 1e-9f
#define IMAX 0x7fffffff

#define GRID_CTAS (148 * 6)
#define TOT_WARPS (GRID_CTAS * 8)

#define G_FILL ((EE + 255) / 256)     // 6250
#define G_GEMM ((NN + 63) / 64)       // 1563

// ---- static device scratch (no allocation allowed) ----
// NOTE: sentinel rows (index NN) of g_h/g_A1/g_A2/g_A3 are zero from static
// initialization and are never written — all writers guard row < NN.
__device__ float g_h[(NN + 1) * D];
__device__ float g_A1[(NN + 1) * D];
__device__ float g_A2[(NN + 1) * D];
__device__ float g_A3[(NN + 1) * D];
__device__ float g_Suh[NN * D];
__device__ float g_SuA1[NN * D];
__device__ int   g_deg[NN];
__device__ int   g_cursor[NN];   // zero at load; re-zeroed by k_fused after sortu
__device__ float g_Su[NN];
__device__ float g_Su2[NN];
__device__ int   g_csr[(size_t)NN * MAXD];   // byte offsets (s * 256) after sort phase
__device__ float g_uS[(size_t)NN * MAXD];
__device__ int      g_bar_count;
__device__ unsigned g_bar_gen;

__device__ __forceinline__ float4 f4zero() { return make_float4(0.f, 0.f, 0.f, 0.f); }
__device__ __forceinline__ void f4acc(float4& a, const float4 v) {
    a.x += v.x; a.y += v.y; a.z += v.z; a.w += v.w;
}
__device__ __forceinline__ void f4fma(float4& a, float c, const float4 v) {
    a.x = fmaf(c, v.x, a.x); a.y = fmaf(c, v.y, a.y);
    a.z = fmaf(c, v.z, a.z); a.w = fmaf(c, v.w, a.w);
}
__device__ __forceinline__ void f4xor16(float4& a) {
    a.x += __shfl_xor_sync(0xffffffffu, a.x, 16);
    a.y += __shfl_xor_sync(0xffffffffu, a.y, 16);
    a.z += __shfl_xor_sync(0xffffffffu, a.z, 16);
    a.w += __shfl_xor_sync(0xffffffffu, a.w, 16);
}
__device__ __forceinline__ float u_of_deg(int dg, float lam) {
    return (dg <= 1) ? 0.f : lam / ((float)dg - 1.0f + EPSF);
}

// counter+generation grid barrier; all GRID_CTAS co-resident by __launch_bounds__
__device__ __forceinline__ void grid_sync() {
    __syncthreads();
    if (threadIdx.x == 0) {
        unsigned gen = *((volatile unsigned*)&g_bar_gen);
        __threadfence();
        if (atomicAdd(&g_bar_count, 1) == GRID_CTAS - 1) {
            g_bar_count = 0;
            __threadfence();
            atomicExch(&g_bar_gen, gen + 1);   // release
        } else {
            while (*((volatile unsigned*)&g_bar_gen) == gen) __nanosleep(64);
        }
        __threadfence();
    }
    __syncthreads();
}

// ======== combined prep: fill blocks [0, G_FILL) + gemm blocks [G_FILL, G_FILL+G_GEMM) ========
__global__ void __launch_bounds__(256) k_prep(const float* __restrict__ x,
                                              const float* __restrict__ W,
                                              const float* __restrict__ b,
                                              const int* __restrict__ src,
                                              const int* __restrict__ dst) {
    int tid = threadIdx.x;
    if (blockIdx.x < G_FILL) {
        // ---- CSR fill (cursor pre-zeroed: static init on run 1, k_fused on replays) ----
        int e = blockIdx.x * 256 + tid;
        if (e < EE) {
            int d = dst[e];
            int pos = atomicAdd(&g_cursor[d], 1);
            if (pos < MAXD) g_csr[(size_t)d * MAXD + pos] = src[e];
        }
        return;
    }
    // ---- register-tiled GEMM: 64x64 tile, 4x4 per thread ----
    __shared__ float xs[D][68];
    __shared__ float Ws[D * D];
    __shared__ float bs[D];
    int bx = blockIdx.x - G_FILL;
    int base = bx * 64;

    for (int i = tid; i < D * D / 4; i += 256)
        ((float4*)Ws)[i] = ((const float4*)W)[i];
    if (tid < D) bs[tid] = b[tid];

    for (int idx = tid; idx < 64 * 16; idx += 256) {
        int row = idx >> 4, c4 = idx & 15;
        int grow = base + row;
        float4 v = (grow < NN) ? *(const float4*)(x + (size_t)grow * D + c4 * 4) : f4zero();
        xs[c4 * 4 + 0][row] = v.x;
        xs[c4 * 4 + 1][row] = v.y;
        xs[c4 * 4 + 2][row] = v.z;
        xs[c4 * 4 + 3][row] = v.w;
    }
    __syncthreads();

    int tr = tid >> 4, tc = tid & 15;
    float acc[4][4];
#pragma unroll
    for (int i = 0; i < 4; i++) {
        acc[i][0] = bs[tc * 4 + 0];
        acc[i][1] = bs[tc * 4 + 1];
        acc[i][2] = bs[tc * 4 + 2];
        acc[i][3] = bs[tc * 4 + 3];
    }
#pragma unroll 8
    for (int k = 0; k < D; k++) {
        float4 a = *(const float4*)&xs[k][tr * 4];
        float4 wv = *(const float4*)&Ws[k * D + tc * 4];
        acc[0][0] = fmaf(a.x, wv.x, acc[0][0]); acc[0][1] = fmaf(a.x, wv.y, acc[0][1]);
        acc[0][2] = fmaf(a.x, wv.z, acc[0][2]); acc[0][3] = fmaf(a.x, wv.w, acc[0][3]);
        acc[1][0] = fmaf(a.y, wv.x, acc[1][0]); acc[1][1] = fmaf(a.y, wv.y, acc[1][1]);
        acc[1][2] = fmaf(a.y, wv.z, acc[1][2]); acc[1][3] = fmaf(a.y, wv.w, acc[1][3]);
        acc[2][0] = fmaf(a.z, wv.x, acc[2][0]); acc[2][1] = fmaf(a.z, wv.y, acc[2][1]);
        acc[2][2] = fmaf(a.z, wv.z, acc[2][2]); acc[2][3] = fmaf(a.z, wv.w, acc[2][3]);
        acc[3][0] = fmaf(a.w, wv.x, acc[3][0]); acc[3][1] = fmaf(a.w, wv.y, acc[3][1]);
        acc[3][2] = fmaf(a.w, wv.z, acc[3][2]); acc[3][3] = fmaf(a.w, wv.w, acc[3][3]);
    }
#pragma unroll
    for (int i = 0; i < 4; i++) {
        int row = base + tr * 4 + i;
        if (row < NN)
            *(float4*)(g_h + (size_t)row * D + tc * 4) =
                make_float4(acc[i][0], acc[i][1], acc[i][2], acc[i][3]);
    }
}

// ================= fused persistent kernel: sort + 4 passes =================

__device__ __forceinline__ void phase_sortu(int n, int lane, float lam) {
    int dg = min(g_cursor[n], MAXD);
    const size_t base = (size_t)n * MAXD;
    float u0 = 0.f, u1 = 0.f;

    if (dg <= 32) {
        int v0 = (lane < dg) ? g_csr[base + lane] : IMAX;
#pragma unroll
        for (int k = 2; k <= 32; k <<= 1) {
#pragma unroll
            for (int j = k >> 1; j > 0; j >>= 1) {
                int p = __shfl_xor_sync(0xffffffffu, v0, j);
                bool up = ((lane & j) == 0);
                bool dir = ((lane & k) == 0) || (k == 32);
                v0 = (up == dir) ? min(v0, p) : max(v0, p);
            }
        }
        if (lane < dg) {
            int c0 = min(__ldg(&g_cursor[v0]), MAXD);
            u0 = u_of_deg(c0, lam);
            g_csr[base + lane] = v0 << 8;
            g_uS[base + lane] = u0;
        }
    } else {
        int v0 = (lane < dg) ? g_csr[base + lane] : IMAX;
        int v1 = (lane + 32 < dg) ? g_csr[base + lane + 32] : IMAX;
#pragma unroll
        for (int k = 2; k <= 64; k <<= 1) {
#pragma unroll
            for (int j = k >> 1; j > 0; j >>= 1) {
                if (j == 32) {
                    bool dir = ((lane & k) == 0) || (k == 64);
                    int lo = min(v0, v1), hi = max(v0, v1);
                    v0 = dir ? lo : hi;
                    v1 = dir ? hi : lo;
                } else {
                    int p0 = __shfl_xor_sync(0xffffffffu, v0, j);
                    bool up0 = ((lane & j) == 0);
                    bool dir0 = ((lane & k) == 0) || (k == 64);
                    v0 = (up0 == dir0) ? min(v0, p0) : max(v0, p0);
                    int p1 = __shfl_xor_sync(0xffffffffu, v1, j);
                    int idx1 = lane + 32;
                    bool up1 = ((idx1 & j) == 0);
                    bool dir1 = ((idx1 & k) == 0) || (k == 64);
                    v1 = (up1 == dir1) ? min(v1, p1) : max(v1, p1);
                }
            }
        }
        if (lane < dg) {
            int c0 = min(__ldg(&g_cursor[v0]), MAXD);
            u0 = u_of_deg(c0, lam);
            g_csr[base + lane] = v0 << 8;
            g_uS[base + lane] = u0;
        }
        if (lane + 32 < dg) {
            int c1 = min(__ldg(&g_cursor[v1]), MAXD);
            u1 = u_of_deg(c1, lam);
            g_csr[base + lane + 32] = v1 << 8;
            g_uS[base + lane + 32] = u1;
        }
    }
    if (lane < 2 && dg + lane < MAXD) {
        g_csr[base + dg + lane] = NN << 8;
        g_uS[base + dg + lane] = 0.f;
    }
    float suL = u0 + u1;
    float su2L = u0 * u0 + u1 * u1;
    for (int o = 16; o > 0; o >>= 1) {
        suL += __shfl_xor_sync(0xffffffffu, suL, o);
        su2L += __shfl_xor_sync(0xffffffffu, su2L, o);
    }
    if (lane == 0) { g_deg[n] = dg; g_Su[n] = suL; g_Su2[n] = su2L; }
}

__device__ __forceinline__ void phase_p1(int n, int w, int lane, float lam,
                                         int (*sI)[MAXD], float (*sU)[MAXD]) {
    int dg = g_deg[n];
    int dgp = (dg + 1) & ~1;
    const size_t base = (size_t)n * MAXD;
    for (int i = lane; i < dgp; i += 32) {
        sI[w][i] = g_csr[base + i];
        sU[w][i] = g_uS[base + i];
    }
    __syncwarp();
    int half = lane >> 4, sub = lane & 15;
    const char* hb = (const char*)g_h + sub * 16;
    float4 m0 = f4zero(), suh = f4zero();
#pragma unroll 4
    for (int it = half; it < dgp; it += 2) {
        int off = sI[w][it];
        float us = sU[w][it];
        float4 v = *(const float4*)(hb + off);
        f4acc(m0, v);
        f4fma(suh, us, v);
    }
    f4xor16(m0); f4xor16(suh);
    if (lane < 16) {
        float ud = u_of_deg(dg, lam);
        float4 hd = *(const float4*)(g_h + (size_t)n * D + sub * 4);
        float4 a1;
        if (dg == 1) a1 = hd;
        else {
            a1.x = (1.f - lam) * hd.x + ud * m0.x;
            a1.y = (1.f - lam) * hd.y + ud * m0.y;
            a1.z = (1.f - lam) * hd.z + ud * m0.z;
            a1.w = (1.f - lam) * hd.w + ud * m0.w;
        }
        *(float4*)(g_A1 + (size_t)n * D + sub * 4) = a1;
        *(float4*)(g_Suh + (size_t)n * D + sub * 4) = suh;
    }
    __syncwarp();
}

__device__ __forceinline__ void phase_p2(int n, int w, int lane, float lam,
                                         int (*sI)[MAXD], float (*sU)[MAXD]) {
    int dg = g_deg[n];
    int dgp = (dg + 1) & ~1;
    const size_t base = (size_t)n * MAXD;
    for (int i = lane; i < dgp; i += 32) {
        sI[w][i] = g_csr[base + i];
        sU[w][i] = g_uS[base + i];
    }
    __syncwarp();
    int half = lane >> 4, sub = lane & 15;
    const char* ab = (const char*)g_A1 + sub * 16;
    float4 sa1 = f4zero(), sua1 = f4zero();
#pragma unroll 4
    for (int it = half; it < dgp; it += 2) {
        int off = sI[w][it];
        float us = sU[w][it];
        float4 v = *(const float4*)(ab + off);
        f4acc(sa1, v);
        f4fma(sua1, us, v);
    }
    f4xor16(sa1); f4xor16(sua1);
    if (lane < 16) {
        float su = g_Su[n];
        float ud = u_of_deg(dg, lam);
        float4 hd = *(const float4*)(g_h + (size_t)n * D + sub * 4);
        float4 a2;
        if (dg == 1) a2 = hd;
        else {
            a2.x = (1.f - lam) * hd.x + ud * (sa1.x - su * hd.x);
            a2.y = (1.f - lam) * hd.y + ud * (sa1.y - su * hd.y);
            a2.z = (1.f - lam) * hd.z + ud * (sa1.z - su * hd.z);
            a2.w = (1.f - lam) * hd.w + ud * (sa1.w - su * hd.w);
        }
        *(float4*)(g_A2 + (size_t)n * D + sub * 4) = a2;
        *(float4*)(g_SuA1 + (size_t)n * D + sub * 4) = sua1;
    }
    __syncwarp();
}

__device__ __forceinline__ void phase_p3(int n, int w, int lane, float lam,
                                         int (*sI)[MAXD]) {
    int dg = g_deg[n];
    int dgp = (dg + 1) & ~1;
    const size_t base = (size_t)n * MAXD;
    for (int i = lane; i < dgp; i += 32) sI[w][i] = g_csr[base + i];
    __syncwarp();
    int half = lane >> 4, sub = lane & 15;
    const char* ab = (const char*)g_A2 + sub * 16;
    float4 sa2 = f4zero();
#pragma unroll 4
    for (int it = half; it < dgp; it += 2) {
        int off = sI[w][it];
        float4 v = *(const float4*)(ab + off);
        f4acc(sa2, v);
    }
    f4xor16(sa2);
    if (lane < 16) {
        float su = g_Su[n];
        float ud = u_of_deg(dg, lam);
        float4 hd = *(const float4*)(g_h + (size_t)n * D + sub * 4);
        float4 a1d = *(const float4*)(g_A1 + (size_t)n * D + sub * 4);
        float4 suhd = *(const float4*)(g_Suh + (size_t)n * D + sub * 4);
        float4 a3;
        if (dg == 1) a3 = hd;
        else {
            a3.x = (1.f - lam) * hd.x + ud * (sa2.x - su * a1d.x + ud * suhd.x);
            a3.y = (1.f - lam) * hd.y + ud * (sa2.y - su * a1d.y + ud * suhd.y);
            a3.z = (1.f - lam) * hd.z + ud * (sa2.z - su * a1d.z + ud * suhd.z);
            a3.w = (1.f - lam) * hd.w + ud * (sa2.w - su * a1d.w + ud * suhd.w);
        }
        *(float4*)(g_A3 + (size_t)n * D + sub * 4) = a3;
    }
    __syncwarp();
}

__device__ __forceinline__ void phase_p4(int n, int w, int lane, float lam,
                                         const float* __restrict__ x,
                                         float* __restrict__ out,
                                         int (*sI)[MAXD]) {
    int dg = g_deg[n];
    int dgp = (dg + 1) & ~1;
    const size_t base = (size_t)n * MAXD;
    for (int i = lane; i < dgp; i += 32) sI[w][i] = g_csr[base + i];
    __syncwarp();
    int half = lane >> 4, sub = lane & 15;
    const char* ab = (const char*)g_A3 + sub * 16;
    float4 sa3 = f4zero();
#pragma unroll 4
    for (int it = half; it < dgp; it += 2) {
        int off = sI[w][it];
        float4 v = *(const float4*)(ab + off);
        f4acc(sa3, v);
    }
    f4xor16(sa3);
    if (lane < 16) {
        float su = g_Su[n];
        float su2 = g_Su2[n];
        float ud = u_of_deg(dg, lam);
        float4 hd = *(const float4*)(g_h + (size_t)n * D + sub * 4);
        float4 a2d = *(const float4*)(g_A2 + (size_t)n * D + sub * 4);
        float4 sua1d = *(const float4*)(g_SuA1 + (size_t)n * D + sub * 4);
        float4 xd = *(const float4*)(x + (size_t)n * D + sub * 4);
        float4 tmp;
        if (dg == 0) {
            tmp = hd;
        } else {
            float c = lam / ((float)dg + EPSF);
            float us2 = ud * su2;
            tmp.x = (1.f - lam) * hd.x + c * (sa3.x - su * a2d.x + ud * sua1d.x - us2 * hd.x);
            tmp.y = (1.f - lam) * hd.y + c * (sa3.y - su * a2d.y + ud * sua1d.y - us2 * hd.y);
            tmp.z = (1.f - lam) * hd.z + c * (sa3.z - su * a2d.z + ud * sua1d.z - us2 * hd.z);
            tmp.w = (1.f - lam) * hd.w + c * (sa3.w - su * a2d.w + ud * sua1d.w - us2 * hd.w);
        }
        float4 o;
        o.x = xd.x + fmaxf(tmp.x, 0.f);
        o.y = xd.y + fmaxf(tmp.y, 0.f);
        o.z = xd.z + fmaxf(tmp.z, 0.f);
        o.w = xd.w + fmaxf(tmp.w, 0.f);
        *(float4*)(out + (size_t)n * D + sub * 4) = o;
    }
    __syncwarp();
}

__global__ void __launch_bounds__(256, 6)
k_fused(const float* __restrict__ lm, const float* __restrict__ x,
        float* __restrict__ out) {
    __shared__ int sI[8][MAXD];
    __shared__ float sU[8][MAXD];
    int w = threadIdx.x >> 5;
    int lane = threadIdx.x & 31;
    int wid0 = (blockIdx.x * 256 + threadIdx.x) >> 5;
    float lam = lm[0];

    for (int n = wid0; n < NN; n += TOT_WARPS) phase_sortu(n, lane, lam);
    grid_sync();
    // re-zero cursor for the next graph replay (sortu is done with it)
    for (int i = blockIdx.x * 256 + threadIdx.x; i < NN; i += GRID_CTAS * 256)
        g_cursor[i] = 0;
    for (int n = wid0; n < NN; n += TOT_WARPS) phase_p1(n, w, lane, lam, sI, sU);
    grid_sync();
    for (int n = wid0; n < NN; n += TOT_WARPS) phase_p2(n, w, lane, lam, sI, sU);
    grid_sync();
    for (int n = wid0; n < NN; n += TOT_WARPS) phase_p3(n, w, lane, lam, sI);
    grid_sync();
    for (int n = wid0; n < NN; n += TOT_WARPS) phase_p4(n, w, lane, lam, x, out, sI);
}

extern "C" void kernel_launch(void* const* d_in, const int* in_sizes, int n_in,
                              void* d_out, int out_size) {
    const float* x = (const float*)d_in[0];
    const int* edge_index = (const int*)d_in[1];
    const float* W = (const float*)d_in[2];
    const float* b = (const float*)d_in[3];
    const float* lm = (const float*)d_in[4];
    float* out = (float*)d_out;

    const int* src = edge_index;        // row 0
    const int* dst = edge_index + EE;   // row 1

    k_prep<<<G_FILL + G_GEMM, 256>>>(x, W, b, src, dst);
    k_fused<<<GRID_CTAS, 256>>>(lm, x, out);
}